// round 1
// baseline (speedup 1.0000x reference)
#include <cuda_runtime.h>
#include <math.h>

// ---------------------------------------------------------------------------
// Problem dims
// ---------------------------------------------------------------------------
#define TOK    4096   // B*S*T = 8*32*16
#define BATCH  8
#define SEQ    512    // S*T
#define Dm     256
#define Hh     8
#define DHd    32
#define FFd    1024
#define Np     256    // B*S points
#define ENCIN  4096   // T*D
#define Kc     5

// ---------------------------------------------------------------------------
// Scratch (static device globals — no allocation allowed)
// ---------------------------------------------------------------------------
__device__ float g_z [TOK * Dm];
__device__ float g_q [TOK * Dm];
__device__ float g_k [TOK * Dm];
__device__ float g_v [TOK * Dm];
__device__ float g_o [TOK * Dm];
__device__ float g_f [TOK * Dm];
__device__ float g_h1[TOK * FFd];
__device__ float g_h1e[Np * 128];
__device__ float g_low[Np * 2];
__device__ float g_hd [Np * 128];
__device__ float g_dsq[Np];
__device__ int   g_idx[Np];
__device__ float g_recpart[Np];

// ---------------------------------------------------------------------------
// Block-wide sum for 256-thread blocks (result broadcast to all threads)
// ---------------------------------------------------------------------------
__device__ __forceinline__ float blockSum256(float v) {
    __shared__ float red[8];
#pragma unroll
    for (int o = 16; o; o >>= 1) v += __shfl_xor_sync(0xffffffffu, v, o);
    if ((threadIdx.x & 31) == 0) red[threadIdx.x >> 5] = v;
    __syncthreads();
    float s = red[0] + red[1] + red[2] + red[3] + red[4] + red[5] + red[6] + red[7];
    __syncthreads();
    return s;
}

// ---------------------------------------------------------------------------
// Embedding: z[n,d] = sum_f x_seg[n,f]*emb_W[f,d] + emb_b[d]
// ---------------------------------------------------------------------------
__global__ void embed_kernel(const float* __restrict__ x, const float* __restrict__ W,
                             const float* __restrict__ b, float* __restrict__ z) {
    int n = blockIdx.x, d = threadIdx.x;
    float acc = b[d];
#pragma unroll
    for (int f = 0; f < 8; f++) acc += x[n * 8 + f] * W[f * Dm + d];
    z[(size_t)n * Dm + d] = acc;
}

// ---------------------------------------------------------------------------
// Tiled fp32 GEMM: C[M,N] = A[M,K] @ B[K,N] (+bias)(+relu)
// BM=BN=64, BK=16, 256 threads, 4x4 per-thread tile.
// Requires M%64==0, N%64==0, K%16==0 (true for all call sites).
// mode: 0 = none, 1 = +bias, 2 = +bias then relu
// ---------------------------------------------------------------------------
__global__ void __launch_bounds__(256) gemm_kernel(
        const float* __restrict__ A, const float* __restrict__ B,
        const float* __restrict__ bias, float* __restrict__ C,
        int M, int N, int K, int mode) {
    __shared__ float As[16][65];
    __shared__ float Bs[16][64];
    int tid = threadIdx.x;
    int bm = blockIdx.y << 6, bn = blockIdx.x << 6;
    int tx = tid & 15, ty = tid >> 4;
    int arow = tid >> 2, acol = (tid & 3) << 2;
    int brow = tid >> 4, bcol = (tid & 15) << 2;

    float acc[4][4] = {};
    for (int k0 = 0; k0 < K; k0 += 16) {
        float4 a4 = *(const float4*)(A + (size_t)(bm + arow) * K + k0 + acol);
        As[acol + 0][arow] = a4.x;
        As[acol + 1][arow] = a4.y;
        As[acol + 2][arow] = a4.z;
        As[acol + 3][arow] = a4.w;
        float4 b4 = *(const float4*)(B + (size_t)(k0 + brow) * N + bn + bcol);
        *(float4*)&Bs[brow][bcol] = b4;
        __syncthreads();
#pragma unroll
        for (int kk = 0; kk < 16; kk++) {
            float a0 = As[kk][(ty << 2) + 0];
            float a1 = As[kk][(ty << 2) + 1];
            float a2 = As[kk][(ty << 2) + 2];
            float a3 = As[kk][(ty << 2) + 3];
            float4 b = *(const float4*)&Bs[kk][tx << 2];
            acc[0][0] += a0 * b.x; acc[0][1] += a0 * b.y; acc[0][2] += a0 * b.z; acc[0][3] += a0 * b.w;
            acc[1][0] += a1 * b.x; acc[1][1] += a1 * b.y; acc[1][2] += a1 * b.z; acc[1][3] += a1 * b.w;
            acc[2][0] += a2 * b.x; acc[2][1] += a2 * b.y; acc[2][2] += a2 * b.z; acc[2][3] += a2 * b.w;
            acc[3][0] += a3 * b.x; acc[3][1] += a3 * b.y; acc[3][2] += a3 * b.z; acc[3][3] += a3 * b.w;
        }
        __syncthreads();
    }
    float4 bb = make_float4(0.f, 0.f, 0.f, 0.f);
    if (mode >= 1) bb = *(const float4*)(bias + bn + (tx << 2));
#pragma unroll
    for (int i = 0; i < 4; i++) {
        float4 r;
        r.x = acc[i][0] + bb.x;
        r.y = acc[i][1] + bb.y;
        r.z = acc[i][2] + bb.z;
        r.w = acc[i][3] + bb.w;
        if (mode == 2) {
            r.x = fmaxf(r.x, 0.f); r.y = fmaxf(r.y, 0.f);
            r.z = fmaxf(r.z, 0.f); r.w = fmaxf(r.w, 0.f);
        }
        *(float4*)(C + (size_t)(bm + (ty << 2) + i) * N + bn + (tx << 2)) = r;
    }
}

// ---------------------------------------------------------------------------
// Fused attention: one CTA per (b,h). K/V staged in SMEM; per-warp softmax.
// 512 threads = 16 warps; each warp owns 32 query rows (processed 2 at a time).
// ---------------------------------------------------------------------------
#define ATTN_SMEM_FLOATS (512 * 36 + 512 * 32 + 16 * 1024)
#define ATTN_SMEM_BYTES  (ATTN_SMEM_FLOATS * 4)

__global__ void __launch_bounds__(512, 1) attn_kernel(
        const float* __restrict__ q, const float* __restrict__ k,
        const float* __restrict__ v, float* __restrict__ o) {
    extern __shared__ float sm[];
    float* ks = sm;                 // [512][36]  (padded: conflict-free strided reads)
    float* vs = ks + 512 * 36;      // [512][32]
    float* ps = vs + 512 * 32;      // [16 warps][512 keys][2 rows] packed

    int bh = blockIdx.x;
    int b = bh >> 3, h = bh & 7;
    int tid = threadIdx.x, warp = tid >> 5, lane = tid & 31;
    size_t base = (size_t)b * SEQ * Dm + h * DHd;

    for (int i = tid; i < 512 * 32; i += 512) {
        int n = i >> 5, d = i & 31;
        ks[n * 36 + d] = k[base + (size_t)n * Dm + d];
        vs[n * 32 + d] = v[base + (size_t)n * Dm + d];
    }
    __syncthreads();

    const float scale = 0.17677669529663687f;  // 1/sqrt(32)
    float* pw = ps + warp * 1024;

    for (int rp = 0; rp < 16; rp++) {
        int row0 = (warp << 5) + (rp << 1);
#pragma unroll
        for (int r = 0; r < 2; r++) {
            int row = row0 + r;
            const float* qp = q + base + (size_t)row * Dm;
            float q0[32];
#pragma unroll
            for (int d = 0; d < 32; d++) q0[d] = __ldg(qp + d);
            float sc[16];
            float mx = -1e30f;
#pragma unroll
            for (int i = 0; i < 16; i++) {
                int key = (i << 5) + lane;
                const float* kp = ks + key * 36;
                float s = 0.f;
#pragma unroll
                for (int d4 = 0; d4 < 8; d4++) {
                    float4 kk4 = *(const float4*)(kp + (d4 << 2));
                    s += q0[d4 * 4 + 0] * kk4.x + q0[d4 * 4 + 1] * kk4.y +
                         q0[d4 * 4 + 2] * kk4.z + q0[d4 * 4 + 3] * kk4.w;
                }
                s *= scale;
                sc[i] = s;
                mx = fmaxf(mx, s);
            }
#pragma unroll
            for (int off = 16; off; off >>= 1) mx = fmaxf(mx, __shfl_xor_sync(0xffffffffu, mx, off));
            float sum = 0.f;
#pragma unroll
            for (int i = 0; i < 16; i++) { sc[i] = __expf(sc[i] - mx); sum += sc[i]; }
#pragma unroll
            for (int off = 16; off; off >>= 1) sum += __shfl_xor_sync(0xffffffffu, sum, off);
            float inv = 1.f / sum;
#pragma unroll
            for (int i = 0; i < 16; i++) pw[(((i << 5) + lane) << 1) + r] = sc[i] * inv;
        }
        __syncwarp();
        float acc0 = 0.f, acc1 = 0.f;
#pragma unroll 4
        for (int key = 0; key < 512; key += 2) {
            float4 p = *(const float4*)(pw + (key << 1));  // (k,r0)(k,r1)(k+1,r0)(k+1,r1)
            float v0 = vs[key * 32 + lane];
            float v1 = vs[(key + 1) * 32 + lane];
            acc0 += p.x * v0 + p.z * v1;
            acc1 += p.y * v0 + p.w * v1;
        }
        o[base + (size_t)row0 * Dm + lane]       = acc0;
        o[base + (size_t)(row0 + 1) * Dm + lane] = acc1;
        __syncwarp();
    }
}

// ---------------------------------------------------------------------------
// Residual add + LayerNorm (in-place on z), one block per row, 256 threads.
// ---------------------------------------------------------------------------
__global__ void addln_kernel(float* __restrict__ z, const float* __restrict__ delta,
                             const float* __restrict__ gam, const float* __restrict__ bet) {
    int row = blockIdx.x, tid = threadIdx.x;
    size_t off = (size_t)row * Dm + tid;
    float vv = z[off] + delta[off];
    float mu = blockSum256(vv) * (1.f / 256.f);
    float dv = vv - mu;
    float var = blockSum256(dv * dv) * (1.f / 256.f);
    z[off] = dv * rsqrtf(var + 1e-5f) * gam[tid] + bet[tid];
}

// ---------------------------------------------------------------------------
// Encoder head + decoder hidden + cluster assignment. 1 block, 256 threads
// (one thread per point).
// ---------------------------------------------------------------------------
__global__ void low_kernel(const float* __restrict__ h1e, const float* __restrict__ eW2,
                           const float* __restrict__ eb2, const float* __restrict__ dW1,
                           const float* __restrict__ db1, const float* __restrict__ ctr,
                           float* __restrict__ low, float* __restrict__ hd,
                           int* __restrict__ idxp, float* __restrict__ dsq) {
    __shared__ float w2[256], dw[256], db[128], cc[10];
    int n = threadIdx.x;
    w2[n] = eW2[n];                 // enc_W2 [128,2]
    dw[n] = dW1[n];                 // dec_W1 [2,128]
    if (n < 128) db[n] = db1[n];
    if (n < 10)  cc[n] = ctr[n];
    __syncthreads();

    float a0 = eb2[0], a1 = eb2[1];
    for (int kk = 0; kk < 128; kk++) {
        float hv = h1e[n * 128 + kk];
        a0 += hv * w2[kk * 2 + 0];
        a1 += hv * w2[kk * 2 + 1];
    }
    float l0 = 1.f / (1.f + expf(-a0));
    float l1 = 1.f / (1.f + expf(-a1));
    low[n * 2 + 0] = l0;
    low[n * 2 + 1] = l1;
    for (int m = 0; m < 128; m++) {
        float hv = l0 * dw[m] + l1 * dw[128 + m] + db[m];
        hd[n * 128 + m] = fmaxf(hv, 0.f);
    }
    int best = 0; float bd = 3.4e38f;
#pragma unroll
    for (int c = 0; c < Kc; c++) {
        float dx = l0 - cc[2 * c], dy = l1 - cc[2 * c + 1];
        float d2 = dx * dx + dy * dy;
        if (d2 < bd) { bd = d2; best = c; }   // strict < => first-index tie-break
    }
    idxp[n] = best;
    dsq[n] = bd;
}

// ---------------------------------------------------------------------------
// Reconstruction L1 partial sums: one CTA per point.
// rec[n,f] = relu_hidden[n] . dec_W2[:,f] + dec_b2[f]
// ---------------------------------------------------------------------------
__global__ void recloss_kernel(const float* __restrict__ pts, const float* __restrict__ hd,
                               const float* __restrict__ W2, const float* __restrict__ b2,
                               float* __restrict__ part) {
    int n = blockIdx.x, tid = threadIdx.x;
    __shared__ float hs[128];
    if (tid < 128) hs[tid] = hd[n * 128 + tid];
    __syncthreads();
    float acc = 0.f;
    for (int f = tid; f < ENCIN; f += 256) {
        float r = b2[f];
#pragma unroll 8
        for (int kk = 0; kk < 128; kk++) r += hs[kk] * W2[(size_t)kk * ENCIN + f];
        acc += fabsf(pts[(size_t)n * ENCIN + f] - r);
    }
    float s = blockSum256(acc);
    if (tid == 0) part[n] = s;
}

// ---------------------------------------------------------------------------
// Final losses + output assembly. 1 block, 256 threads.
// Output layout: [loss, kl, idx(256 as float), low(512)]
// ---------------------------------------------------------------------------
__global__ void final_kernel(const float* __restrict__ dsq, const int* __restrict__ idxp,
                             const float* __restrict__ low, const float* __restrict__ recpart,
                             float* __restrict__ out, int out_size) {
    __shared__ float sums[Kc], cnts[Kc];
    int tid = threadIdx.x;
    float d = dsq[tid];
    int my = idxp[tid];

    float inter = blockSum256(d) * (1.f / 256.f);

    if (tid < Kc) { sums[tid] = 0.f; cnts[tid] = 0.f; }
    __syncthreads();
    atomicAdd(&sums[my], d);
    atomicAdd(&cnts[my], 1.f);
    __syncthreads();

    // scatter arr = zeros.at[idx].set(100): position i gets 100 iff i appears in idx
    bool mem = false;
    for (int j = 0; j < 256; j++) {
        if (idxp[j] == tid) { mem = true; break; }
    }
    float arr = mem ? 100.f : 0.f;

    // log_softmax (max is exactly 100: idx values < K <= 256 so members exist)
    float se = blockSum256(expf(arr - 100.f));
    float lse = logf(se) + 100.f;
    float logp = arr - lse;

    float klsum = blockSum256(-logf(256.f) - logp);
    float kl = klsum * (1.f / (256.f * 256.f));

    float rec = blockSum256(recpart[tid]) * (1.f / (256.f * 4096.f));

    if (tid == 0) {
        float intra = 0.f, ne = 0.f;
#pragma unroll
        for (int c = 0; c < Kc; c++) {
            if (cnts[c] > 0.f) { intra += sums[c] / fmaxf(cnts[c], 1.f); ne += 1.f; }
        }
        intra /= fmaxf(ne, 1.f);
        float loss = inter + intra + kl + rec;
        if (out_size > 0) out[0] = loss;
        if (out_size > 1) out[1] = kl;
    }
    if (2 + tid < out_size) out[2 + tid] = (float)my;
    int p0 = 258 + 2 * tid;
    if (p0 < out_size)     out[p0]     = low[2 * tid];
    if (p0 + 1 < out_size) out[p0 + 1] = low[2 * tid + 1];
}

// ---------------------------------------------------------------------------
// Host launcher
// ---------------------------------------------------------------------------
extern "C" void kernel_launch(void* const* d_in, const int* in_sizes, int n_in,
                              void* d_out, int out_size) {
    const float* x_seg  = (const float*)d_in[1];
    const float* emb_W  = (const float*)d_in[2];
    const float* emb_b  = (const float*)d_in[3];
    const float* Wq     = (const float*)d_in[4];
    const float* Wk     = (const float*)d_in[5];
    const float* Wv     = (const float*)d_in[6];
    const float* Wo     = (const float*)d_in[7];
    const float* W1     = (const float*)d_in[8];
    const float* b1     = (const float*)d_in[9];
    const float* W2     = (const float*)d_in[10];
    const float* b2     = (const float*)d_in[11];
    const float* ln1_g  = (const float*)d_in[12];
    const float* ln1_b  = (const float*)d_in[13];
    const float* ln2_g  = (const float*)d_in[14];
    const float* ln2_b  = (const float*)d_in[15];
    const float* enc_W1 = (const float*)d_in[16];
    const float* enc_b1 = (const float*)d_in[17];
    const float* enc_W2 = (const float*)d_in[18];
    const float* enc_b2 = (const float*)d_in[19];
    const float* dec_W1 = (const float*)d_in[20];
    const float* dec_b1 = (const float*)d_in[21];
    const float* dec_W2 = (const float*)d_in[22];
    const float* dec_b2 = (const float*)d_in[23];
    const float* centers = (const float*)d_in[24];

    float *z, *q, *k, *v, *o, *f, *h1, *h1e, *low, *hd, *dsq, *recpart;
    int* idxp;
    cudaGetSymbolAddress((void**)&z,   g_z);
    cudaGetSymbolAddress((void**)&q,   g_q);
    cudaGetSymbolAddress((void**)&k,   g_k);
    cudaGetSymbolAddress((void**)&v,   g_v);
    cudaGetSymbolAddress((void**)&o,   g_o);
    cudaGetSymbolAddress((void**)&f,   g_f);
    cudaGetSymbolAddress((void**)&h1,  g_h1);
    cudaGetSymbolAddress((void**)&h1e, g_h1e);
    cudaGetSymbolAddress((void**)&low, g_low);
    cudaGetSymbolAddress((void**)&hd,  g_hd);
    cudaGetSymbolAddress((void**)&dsq, g_dsq);
    cudaGetSymbolAddress((void**)&idxp, g_idx);
    cudaGetSymbolAddress((void**)&recpart, g_recpart);

    cudaFuncSetAttribute(attn_kernel, cudaFuncAttributeMaxDynamicSharedMemorySize,
                         ATTN_SMEM_BYTES);

    embed_kernel<<<TOK, 256>>>(x_seg, emb_W, emb_b, z);

    for (int l = 0; l < 2; l++) {
        dim3 gProj(Dm / 64, TOK / 64);           // (4, 64)
        gemm_kernel<<<gProj, 256>>>(z, Wq + (size_t)l * Dm * Dm, nullptr, q, TOK, Dm, Dm, 0);
        gemm_kernel<<<gProj, 256>>>(z, Wk + (size_t)l * Dm * Dm, nullptr, k, TOK, Dm, Dm, 0);
        gemm_kernel<<<gProj, 256>>>(z, Wv + (size_t)l * Dm * Dm, nullptr, v, TOK, Dm, Dm, 0);

        attn_kernel<<<BATCH * Hh, 512, ATTN_SMEM_BYTES>>>(q, k, v, o);

        gemm_kernel<<<gProj, 256>>>(o, Wo + (size_t)l * Dm * Dm, nullptr, q, TOK, Dm, Dm, 0);
        addln_kernel<<<TOK, 256>>>(z, q, ln1_g + l * Dm, ln1_b + l * Dm);

        gemm_kernel<<<dim3(FFd / 64, TOK / 64), 256>>>(
            z, W1 + (size_t)l * Dm * FFd, b1 + l * FFd, h1, TOK, FFd, Dm, 2);
        gemm_kernel<<<dim3(Dm / 64, TOK / 64), 256>>>(
            h1, W2 + (size_t)l * FFd * Dm, b2 + l * Dm, f, TOK, Dm, FFd, 1);
        addln_kernel<<<TOK, 256>>>(z, f, ln2_g + l * Dm, ln2_b + l * Dm);
    }

    // encoder hidden: [256,4096] @ [4096,128] + bias, relu
    gemm_kernel<<<dim3(128 / 64, Np / 64), 256>>>(z, enc_W1, enc_b1, h1e, Np, 128, ENCIN, 2);

    low_kernel<<<1, 256>>>(h1e, enc_W2, enc_b2, dec_W1, dec_b1, centers,
                           low, hd, idxp, dsq);
    recloss_kernel<<<Np, 256>>>(z, hd, dec_W2, dec_b2, recpart);
    final_kernel<<<1, 256>>>(dsq, idxp, low, recpart, (float*)d_out, out_size);
}

// round 2
// speedup vs baseline: 2.2252x; 2.2252x over previous
#include <cuda_runtime.h>
#include <math.h>

// ---------------------------------------------------------------------------
// Problem dims
// ---------------------------------------------------------------------------
#define TOK    4096   // B*S*T
#define BATCH  8
#define SEQ    512
#define Dm     256
#define Hh     8
#define DHd    32
#define FFd    1024
#define Np     256
#define ENCIN  4096
#define Kc     5

// ---------------------------------------------------------------------------
// Scratch
// ---------------------------------------------------------------------------
__device__ float g_z [TOK * Dm];
__device__ float g_q [TOK * Dm];
__device__ float g_k [TOK * Dm];
__device__ float g_v [TOK * Dm];
__device__ float g_o [TOK * Dm];
__device__ float g_f [TOK * Dm];
__device__ float g_h1[TOK * FFd];
__device__ float g_encpart[16 * Np * 128];
__device__ float g_h1e[Np * 128];
__device__ float g_low[Np * 2];
__device__ float g_hd [Np * 128];
__device__ float g_dsq[Np];
__device__ int   g_idx[Np];
__device__ float g_recpart[Np];

// ---------------------------------------------------------------------------
__device__ __forceinline__ float blockSum256(float v) {
    __shared__ float red[8];
#pragma unroll
    for (int o = 16; o; o >>= 1) v += __shfl_xor_sync(0xffffffffu, v, o);
    if ((threadIdx.x & 31) == 0) red[threadIdx.x >> 5] = v;
    __syncthreads();
    float s = red[0] + red[1] + red[2] + red[3] + red[4] + red[5] + red[6] + red[7];
    __syncthreads();
    return s;
}

__device__ __forceinline__ unsigned f2tf(float f) {
    unsigned u;
    asm("cvt.rna.tf32.f32 %0, %1;" : "=r"(u) : "f"(f));
    return u;
}

// ---------------------------------------------------------------------------
// Embedding
// ---------------------------------------------------------------------------
__global__ void embed_kernel(const float* __restrict__ x, const float* __restrict__ W,
                             const float* __restrict__ b, float* __restrict__ z) {
    int n = blockIdx.x, d = threadIdx.x;
    float acc = b[d];
#pragma unroll
    for (int f = 0; f < 8; f++) acc += x[n * 8 + f] * W[f * Dm + d];
    z[(size_t)n * Dm + d] = acc;
}

// ---------------------------------------------------------------------------
// TF32 tensor-core GEMM: C[M,N] = A[M,K] @ B[K,N] (+bias)(+relu)
// BM=BN=64, BK=16, 128 threads (4 warps, 2x2), each warp 32x32 via m16n8k8.
// ---------------------------------------------------------------------------
__device__ __forceinline__ void gemm_tf32_body(
        const float* __restrict__ A, const float* __restrict__ B,
        const float* __restrict__ bias, float* __restrict__ C,
        int M, int N, int K, int mode) {
    __shared__ unsigned As[64 * 20];   // pad 20: conflict-free frag loads
    __shared__ unsigned Bs[16 * 72];   // pad 72: conflict-free frag loads
    int tid = threadIdx.x, lane = tid & 31, w = tid >> 5;
    int bm = blockIdx.y << 6, bn = blockIdx.x << 6;
    int wr = w >> 1, wc = w & 1;

    float acc[2][4][4];
#pragma unroll
    for (int a = 0; a < 2; a++)
#pragma unroll
        for (int b2_ = 0; b2_ < 4; b2_++)
#pragma unroll
            for (int c = 0; c < 4; c++) acc[a][b2_][c] = 0.f;

    int arow = tid >> 1, acol = (tid & 1) << 3;
    int brow = tid >> 3, bcol = (tid & 7) << 3;
    const float* Aptr = A + (size_t)(bm + arow) * K + acol;
    const float* Bptr = B + (size_t)brow * N + bn + bcol;

    for (int k0 = 0; k0 < K; k0 += 16) {
        float4 a0 = *(const float4*)(Aptr);
        float4 a1 = *(const float4*)(Aptr + 4);
        Aptr += 16;
        float4 b0 = *(const float4*)(Bptr);
        float4 b1 = *(const float4*)(Bptr + 4);
        Bptr += (size_t)16 * N;

        uint4 ua, ub;
        ua.x = f2tf(a0.x); ua.y = f2tf(a0.y); ua.z = f2tf(a0.z); ua.w = f2tf(a0.w);
        ub.x = f2tf(a1.x); ub.y = f2tf(a1.y); ub.z = f2tf(a1.z); ub.w = f2tf(a1.w);
        *(uint4*)&As[arow * 20 + acol]     = ua;
        *(uint4*)&As[arow * 20 + acol + 4] = ub;
        ua.x = f2tf(b0.x); ua.y = f2tf(b0.y); ua.z = f2tf(b0.z); ua.w = f2tf(b0.w);
        ub.x = f2tf(b1.x); ub.y = f2tf(b1.y); ub.z = f2tf(b1.z); ub.w = f2tf(b1.w);
        *(uint4*)&Bs[brow * 72 + bcol]     = ua;
        *(uint4*)&Bs[brow * 72 + bcol + 4] = ub;
        __syncthreads();

#pragma unroll
        for (int ks = 0; ks < 16; ks += 8) {
            unsigned afr[2][4];
#pragma unroll
            for (int mt = 0; mt < 2; mt++) {
                int r = wr * 32 + mt * 16 + (lane >> 2);
                int cc = ks + (lane & 3);
                afr[mt][0] = As[r * 20 + cc];
                afr[mt][1] = As[(r + 8) * 20 + cc];
                afr[mt][2] = As[r * 20 + cc + 4];
                afr[mt][3] = As[(r + 8) * 20 + cc + 4];
            }
#pragma unroll
            for (int nt = 0; nt < 4; nt++) {
                int col = wc * 32 + nt * 8 + (lane >> 2);
                int kk = ks + (lane & 3);
                unsigned bf0 = Bs[kk * 72 + col];
                unsigned bf1 = Bs[(kk + 4) * 72 + col];
#pragma unroll
                for (int mt = 0; mt < 2; mt++) {
                    asm volatile(
                        "mma.sync.aligned.m16n8k8.row.col.f32.tf32.tf32.f32 "
                        "{%0,%1,%2,%3},{%4,%5,%6,%7},{%8,%9},{%0,%1,%2,%3};"
                        : "+f"(acc[mt][nt][0]), "+f"(acc[mt][nt][1]),
                          "+f"(acc[mt][nt][2]), "+f"(acc[mt][nt][3])
                        : "r"(afr[mt][0]), "r"(afr[mt][1]), "r"(afr[mt][2]), "r"(afr[mt][3]),
                          "r"(bf0), "r"(bf1));
                }
            }
        }
        __syncthreads();
    }

#pragma unroll
    for (int mt = 0; mt < 2; mt++) {
        int row = bm + wr * 32 + mt * 16 + (lane >> 2);
#pragma unroll
        for (int nt = 0; nt < 4; nt++) {
            int col = bn + wc * 32 + nt * 8 + ((lane & 3) << 1);
            float bv0 = 0.f, bv1 = 0.f;
            if (mode >= 1) { bv0 = bias[col]; bv1 = bias[col + 1]; }
            float c0 = acc[mt][nt][0] + bv0, c1 = acc[mt][nt][1] + bv1;
            float c2 = acc[mt][nt][2] + bv0, c3 = acc[mt][nt][3] + bv1;
            if (mode == 2) {
                c0 = fmaxf(c0, 0.f); c1 = fmaxf(c1, 0.f);
                c2 = fmaxf(c2, 0.f); c3 = fmaxf(c3, 0.f);
            }
            *(float2*)(C + (size_t)row * N + col)       = make_float2(c0, c1);
            *(float2*)(C + (size_t)(row + 8) * N + col) = make_float2(c2, c3);
        }
    }
}

__global__ void __launch_bounds__(128) gemm_tf32(
        const float* __restrict__ A, const float* __restrict__ B,
        const float* __restrict__ bias, float* __restrict__ C,
        int M, int N, int K, int mode) {
    gemm_tf32_body(A, B, bias, C, M, N, K, mode);
}

__global__ void __launch_bounds__(128) gemm_tf32_qkv(
        const float* __restrict__ A,
        const float* __restrict__ Wq, const float* __restrict__ Wk,
        const float* __restrict__ Wv,
        float* __restrict__ q, float* __restrict__ k, float* __restrict__ v) {
    const float* B; float* C;
    if (blockIdx.z == 0)      { B = Wq; C = q; }
    else if (blockIdx.z == 1) { B = Wk; C = k; }
    else                      { B = Wv; C = v; }
    gemm_tf32_body(A, B, nullptr, C, TOK, Dm, Dm, 0);
}

// ---------------------------------------------------------------------------
// fp32 split-K GEMM (encoder path — kept exact). 256 thr, 64x64x16, 4x4.
// blockIdx.z = K-chunk. Writes partials Cp[z][M*N].
// ---------------------------------------------------------------------------
__global__ void __launch_bounds__(256) gemm_splitk(
        const float* __restrict__ A, int lda, const float* __restrict__ B, int ldb,
        float* __restrict__ Cp, int M, int N, int Kchunk) {
    __shared__ float As[16][65];
    __shared__ float Bs[16][64];
    int zc = blockIdx.z;
    A  += zc * Kchunk;
    B  += (size_t)zc * Kchunk * ldb;
    Cp += (size_t)zc * M * N;
    int tid = threadIdx.x;
    int bm = blockIdx.y << 6, bn = blockIdx.x << 6;
    int tx = tid & 15, ty = tid >> 4;
    int arow = tid >> 2, acol = (tid & 3) << 2;
    int brow = tid >> 4, bcol = (tid & 15) << 2;

    float acc[4][4] = {};
    for (int k0 = 0; k0 < Kchunk; k0 += 16) {
        float4 a4 = *(const float4*)(A + (size_t)(bm + arow) * lda + k0 + acol);
        As[acol + 0][arow] = a4.x; As[acol + 1][arow] = a4.y;
        As[acol + 2][arow] = a4.z; As[acol + 3][arow] = a4.w;
        float4 b4 = *(const float4*)(B + (size_t)(k0 + brow) * ldb + bn + bcol);
        *(float4*)&Bs[brow][bcol] = b4;
        __syncthreads();
#pragma unroll
        for (int kk = 0; kk < 16; kk++) {
            float a0 = As[kk][(ty << 2) + 0], a1 = As[kk][(ty << 2) + 1];
            float a2 = As[kk][(ty << 2) + 2], a3 = As[kk][(ty << 2) + 3];
            float4 b = *(const float4*)&Bs[kk][tx << 2];
            acc[0][0] += a0 * b.x; acc[0][1] += a0 * b.y; acc[0][2] += a0 * b.z; acc[0][3] += a0 * b.w;
            acc[1][0] += a1 * b.x; acc[1][1] += a1 * b.y; acc[1][2] += a1 * b.z; acc[1][3] += a1 * b.w;
            acc[2][0] += a2 * b.x; acc[2][1] += a2 * b.y; acc[2][2] += a2 * b.z; acc[2][3] += a2 * b.w;
            acc[3][0] += a3 * b.x; acc[3][1] += a3 * b.y; acc[3][2] += a3 * b.z; acc[3][3] += a3 * b.w;
        }
        __syncthreads();
    }
#pragma unroll
    for (int i = 0; i < 4; i++) {
        float4 r = make_float4(acc[i][0], acc[i][1], acc[i][2], acc[i][3]);
        *(float4*)(Cp + (size_t)(bm + (ty << 2) + i) * N + bn + (tx << 2)) = r;
    }
}

__global__ void enc_reduce(const float* __restrict__ part, const float* __restrict__ bias,
                           float* __restrict__ out) {
    int i = blockIdx.x * 256 + threadIdx.x;   // 0..32767
    float s = bias[i & 127];
#pragma unroll
    for (int c = 0; c < 16; c++) s += part[c * (Np * 128) + i];
    out[i] = fmaxf(s, 0.f);
}

// ---------------------------------------------------------------------------
// Flash attention: CTA = (qtile of 64, bh). 256 threads = 8 warps x 8 queries.
// Keys streamed in 4 chunks of 128, online softmax, all fp32.
// ---------------------------------------------------------------------------
#define AT_SMEM_FLOATS (64 * 32 + 128 * 33 + 128 * 32 + 8 * 1024)
#define AT_SMEM_BYTES  (AT_SMEM_FLOATS * 4)

__global__ void __launch_bounds__(256, 2) attn2(
        const float* __restrict__ qg, const float* __restrict__ kg,
        const float* __restrict__ vg, float* __restrict__ og) {
    extern __shared__ float sm[];
    float* Qs = sm;                       // [64][32]   (scaled)
    float* Ks = Qs + 64 * 32;             // [128][33]
    float* Vs = Ks + 128 * 33;            // [128][32]
    float* Ps = Vs + 128 * 32;            // [8 warps][128*8] layout [k][qi]

    int bh = blockIdx.y, b = bh >> 3, h = bh & 7;
    int qt = blockIdx.x;
    int tid = threadIdx.x, w = tid >> 5, lane = tid & 31;
    size_t base = (size_t)b * SEQ * Dm + h * DHd;
    const float scale = 0.17677669529663687f;

    for (int i = tid; i < 512; i += 256) {        // 64*32/4 float4s
        int row = i >> 3, c4 = (i & 7) << 2;
        float4 t = *(const float4*)(qg + base + (size_t)(qt * 64 + row) * Dm + c4);
        t.x *= scale; t.y *= scale; t.z *= scale; t.w *= scale;
        *(float4*)&Qs[row * 32 + c4] = t;
    }

    int q0 = w * 8;
    float* pw = Ps + w * 1024;
    float m[8], l[8], oacc[8];
#pragma unroll
    for (int i = 0; i < 8; i++) { m[i] = -1e30f; l[i] = 0.f; oacc[i] = 0.f; }

    for (int c = 0; c < 4; c++) {
        __syncthreads();
        for (int i = tid; i < 1024; i += 256) {   // 128*32/4 float4s
            int row = i >> 3, c4 = (i & 7) << 2;
            float4 t = *(const float4*)(kg + base + (size_t)(c * 128 + row) * Dm + c4);
            Ks[row * 33 + c4 + 0] = t.x; Ks[row * 33 + c4 + 1] = t.y;
            Ks[row * 33 + c4 + 2] = t.z; Ks[row * 33 + c4 + 3] = t.w;
            float4 tv = *(const float4*)(vg + base + (size_t)(c * 128 + row) * Dm + c4);
            *(float4*)&Vs[row * 32 + c4] = tv;
        }
        __syncthreads();

        float s[4][8];
#pragma unroll
        for (int i = 0; i < 4; i++)
#pragma unroll
            for (int j = 0; j < 8; j++) s[i][j] = 0.f;

#pragma unroll
        for (int d0 = 0; d0 < 32; d0 += 4) {
            float4 qv[8];
#pragma unroll
            for (int qi = 0; qi < 8; qi++)
                qv[qi] = *(const float4*)&Qs[(q0 + qi) * 32 + d0];
#pragma unroll
            for (int i = 0; i < 4; i++) {
                const float* kp = Ks + (i * 32 + lane) * 33 + d0;
                float k0v = kp[0], k1v = kp[1], k2v = kp[2], k3v = kp[3];
#pragma unroll
                for (int qi = 0; qi < 8; qi++)
                    s[i][qi] += qv[qi].x * k0v + qv[qi].y * k1v +
                                qv[qi].z * k2v + qv[qi].w * k3v;
            }
        }

#pragma unroll
        for (int qi = 0; qi < 8; qi++) {
            float mx = fmaxf(fmaxf(s[0][qi], s[1][qi]), fmaxf(s[2][qi], s[3][qi]));
#pragma unroll
            for (int off = 16; off; off >>= 1) mx = fmaxf(mx, __shfl_xor_sync(0xffffffffu, mx, off));
            float mnew = fmaxf(m[qi], mx);
            float corr = __expf(m[qi] - mnew);
            float ps = 0.f;
#pragma unroll
            for (int i = 0; i < 4; i++) {
                float p = __expf(s[i][qi] - mnew);
                ps += p;
                pw[(i * 32 + lane) * 8 + qi] = p;
            }
#pragma unroll
            for (int off = 16; off; off >>= 1) ps += __shfl_xor_sync(0xffffffffu, ps, off);
            l[qi] = l[qi] * corr + ps;
            m[qi] = mnew;
            oacc[qi] *= corr;
        }
        __syncwarp();
#pragma unroll 4
        for (int kk = 0; kk < 128; kk++) {
            float4 pA = *(const float4*)&pw[kk * 8];
            float4 pB = *(const float4*)&pw[kk * 8 + 4];
            float vv = Vs[kk * 32 + lane];
            oacc[0] += pA.x * vv; oacc[1] += pA.y * vv;
            oacc[2] += pA.z * vv; oacc[3] += pA.w * vv;
            oacc[4] += pB.x * vv; oacc[5] += pB.y * vv;
            oacc[6] += pB.z * vv; oacc[7] += pB.w * vv;
        }
        __syncwarp();
    }
#pragma unroll
    for (int qi = 0; qi < 8; qi++)
        og[base + (size_t)(qt * 64 + q0 + qi) * Dm + lane] = oacc[qi] / l[qi];
}

// ---------------------------------------------------------------------------
// Residual + LayerNorm
// ---------------------------------------------------------------------------
__global__ void addln_kernel(float* __restrict__ z, const float* __restrict__ delta,
                             const float* __restrict__ gam, const float* __restrict__ bet) {
    int row = blockIdx.x, tid = threadIdx.x;
    size_t off = (size_t)row * Dm + tid;
    float vv = z[off] + delta[off];
    float mu = blockSum256(vv) * (1.f / 256.f);
    float dv = vv - mu;
    float var = blockSum256(dv * dv) * (1.f / 256.f);
    z[off] = dv * rsqrtf(var + 1e-5f) * gam[tid] + bet[tid];
}

// ---------------------------------------------------------------------------
// Encoder head + decoder hidden + assignment (exact fp32)
// ---------------------------------------------------------------------------
__global__ void low_kernel(const float* __restrict__ h1e, const float* __restrict__ eW2,
                           const float* __restrict__ eb2, const float* __restrict__ dW1,
                           const float* __restrict__ db1, const float* __restrict__ ctr,
                           float* __restrict__ low, float* __restrict__ hd,
                           int* __restrict__ idxp, float* __restrict__ dsq) {
    __shared__ float w2[256], dw[256], db[128], cc[10];
    int n = threadIdx.x;
    w2[n] = eW2[n];
    dw[n] = dW1[n];
    if (n < 128) db[n] = db1[n];
    if (n < 10)  cc[n] = ctr[n];
    __syncthreads();

    float a0 = eb2[0], a1 = eb2[1];
    for (int kk = 0; kk < 128; kk++) {
        float hv = h1e[n * 128 + kk];
        a0 += hv * w2[kk * 2 + 0];
        a1 += hv * w2[kk * 2 + 1];
    }
    float l0 = 1.f / (1.f + expf(-a0));
    float l1 = 1.f / (1.f + expf(-a1));
    low[n * 2 + 0] = l0;
    low[n * 2 + 1] = l1;
    for (int mm = 0; mm < 128; mm++) {
        float hv = l0 * dw[mm] + l1 * dw[128 + mm] + db[mm];
        hd[n * 128 + mm] = fmaxf(hv, 0.f);
    }
    int best = 0; float bd = 3.4e38f;
#pragma unroll
    for (int c = 0; c < Kc; c++) {
        float dx = l0 - cc[2 * c], dy = l1 - cc[2 * c + 1];
        float d2 = dx * dx + dy * dy;
        if (d2 < bd) { bd = d2; best = c; }
    }
    idxp[n] = best;
    dsq[n] = bd;
}

// ---------------------------------------------------------------------------
// Reconstruction L1: 4 points per CTA (dec_W2 reuse)
// ---------------------------------------------------------------------------
__global__ void __launch_bounds__(256) recloss4(
        const float* __restrict__ pts, const float* __restrict__ hd,
        const float* __restrict__ W2, const float* __restrict__ b2,
        float* __restrict__ part) {
    int n0 = blockIdx.x * 4, tid = threadIdx.x;
    __shared__ float hs[4][128];
    for (int i = tid; i < 512; i += 256) hs[i >> 7][i & 127] = hd[n0 * 128 + i];
    __syncthreads();
    float acc0 = 0.f, acc1 = 0.f, acc2 = 0.f, acc3 = 0.f;
    for (int f = tid; f < ENCIN; f += 256) {
        float bb = b2[f];
        float r0 = bb, r1 = bb, r2 = bb, r3 = bb;
#pragma unroll 4
        for (int kk = 0; kk < 128; kk += 4) {
#pragma unroll
            for (int j = 0; j < 4; j++) {
                float wv = W2[(size_t)(kk + j) * ENCIN + f];
                r0 += hs[0][kk + j] * wv;
                r1 += hs[1][kk + j] * wv;
                r2 += hs[2][kk + j] * wv;
                r3 += hs[3][kk + j] * wv;
            }
        }
        acc0 += fabsf(pts[(size_t)(n0 + 0) * ENCIN + f] - r0);
        acc1 += fabsf(pts[(size_t)(n0 + 1) * ENCIN + f] - r1);
        acc2 += fabsf(pts[(size_t)(n0 + 2) * ENCIN + f] - r2);
        acc3 += fabsf(pts[(size_t)(n0 + 3) * ENCIN + f] - r3);
    }
    float s0 = blockSum256(acc0);
    float s1 = blockSum256(acc1);
    float s2 = blockSum256(acc2);
    float s3 = blockSum256(acc3);
    if (tid == 0) { part[n0] = s0; part[n0 + 1] = s1; part[n0 + 2] = s2; part[n0 + 3] = s3; }
}

// ---------------------------------------------------------------------------
// Final losses + output
// ---------------------------------------------------------------------------
__global__ void final_kernel(const float* __restrict__ dsq, const int* __restrict__ idxp,
                             const float* __restrict__ low, const float* __restrict__ recpart,
                             float* __restrict__ out, int out_size) {
    __shared__ float sums[Kc], cnts[Kc];
    int tid = threadIdx.x;
    float d = dsq[tid];
    int my = idxp[tid];

    float inter = blockSum256(d) * (1.f / 256.f);

    if (tid < Kc) { sums[tid] = 0.f; cnts[tid] = 0.f; }
    __syncthreads();
    atomicAdd(&sums[my], d);
    atomicAdd(&cnts[my], 1.f);
    __syncthreads();

    bool mem = false;
    for (int j = 0; j < 256; j++) {
        if (idxp[j] == tid) { mem = true; break; }
    }
    float arr = mem ? 100.f : 0.f;

    float se = blockSum256(expf(arr - 100.f));
    float lse = logf(se) + 100.f;
    float logp = arr - lse;

    float klsum = blockSum256(-logf(256.f) - logp);
    float kl = klsum * (1.f / (256.f * 256.f));

    float rec = blockSum256(recpart[tid]) * (1.f / (256.f * 4096.f));

    if (tid == 0) {
        float intra = 0.f, ne = 0.f;
#pragma unroll
        for (int c = 0; c < Kc; c++) {
            if (cnts[c] > 0.f) { intra += sums[c] / fmaxf(cnts[c], 1.f); ne += 1.f; }
        }
        intra /= fmaxf(ne, 1.f);
        float loss = inter + intra + kl + rec;
        if (out_size > 0) out[0] = loss;
        if (out_size > 1) out[1] = kl;
    }
    if (2 + tid < out_size) out[2 + tid] = (float)my;
    int p0 = 258 + 2 * tid;
    if (p0 < out_size)     out[p0]     = low[2 * tid];
    if (p0 + 1 < out_size) out[p0 + 1] = low[2 * tid + 1];
}

// ---------------------------------------------------------------------------
// Host launcher
// ---------------------------------------------------------------------------
extern "C" void kernel_launch(void* const* d_in, const int* in_sizes, int n_in,
                              void* d_out, int out_size) {
    const float* x_seg  = (const float*)d_in[1];
    const float* emb_W  = (const float*)d_in[2];
    const float* emb_b  = (const float*)d_in[3];
    const float* Wq     = (const float*)d_in[4];
    const float* Wk     = (const float*)d_in[5];
    const float* Wv     = (const float*)d_in[6];
    const float* Wo     = (const float*)d_in[7];
    const float* W1     = (const float*)d_in[8];
    const float* b1     = (const float*)d_in[9];
    const float* W2     = (const float*)d_in[10];
    const float* b2     = (const float*)d_in[11];
    const float* ln1_g  = (const float*)d_in[12];
    const float* ln1_b  = (const float*)d_in[13];
    const float* ln2_g  = (const float*)d_in[14];
    const float* ln2_b  = (const float*)d_in[15];
    const float* enc_W1 = (const float*)d_in[16];
    const float* enc_b1 = (const float*)d_in[17];
    const float* enc_W2 = (const float*)d_in[18];
    const float* enc_b2 = (const float*)d_in[19];
    const float* dec_W1 = (const float*)d_in[20];
    const float* dec_b1 = (const float*)d_in[21];
    const float* dec_W2 = (const float*)d_in[22];
    const float* dec_b2 = (const float*)d_in[23];
    const float* centers = (const float*)d_in[24];

    float *z, *q, *k, *v, *o, *f, *h1, *encpart, *h1e, *low, *hd, *dsq, *recpart;
    int* idxp;
    cudaGetSymbolAddress((void**)&z,   g_z);
    cudaGetSymbolAddress((void**)&q,   g_q);
    cudaGetSymbolAddress((void**)&k,   g_k);
    cudaGetSymbolAddress((void**)&v,   g_v);
    cudaGetSymbolAddress((void**)&o,   g_o);
    cudaGetSymbolAddress((void**)&f,   g_f);
    cudaGetSymbolAddress((void**)&h1,  g_h1);
    cudaGetSymbolAddress((void**)&encpart, g_encpart);
    cudaGetSymbolAddress((void**)&h1e, g_h1e);
    cudaGetSymbolAddress((void**)&low, g_low);
    cudaGetSymbolAddress((void**)&hd,  g_hd);
    cudaGetSymbolAddress((void**)&dsq, g_dsq);
    cudaGetSymbolAddress((void**)&idxp, g_idx);
    cudaGetSymbolAddress((void**)&recpart, g_recpart);

    cudaFuncSetAttribute(attn2, cudaFuncAttributeMaxDynamicSharedMemorySize,
                         AT_SMEM_BYTES);

    embed_kernel<<<TOK, 256>>>(x_seg, emb_W, emb_b, z);

    for (int l = 0; l < 2; l++) {
        size_t wo = (size_t)l * Dm * Dm;
        gemm_tf32_qkv<<<dim3(4, 64, 3), 128>>>(z, Wq + wo, Wk + wo, Wv + wo, q, k, v);
        attn2<<<dim3(8, 64), 256, AT_SMEM_BYTES>>>(q, k, v, o);
        gemm_tf32<<<dim3(4, 64), 128>>>(o, Wo + wo, nullptr, q, TOK, Dm, Dm, 0);
        addln_kernel<<<TOK, 256>>>(z, q, ln1_g + l * Dm, ln1_b + l * Dm);
        gemm_tf32<<<dim3(16, 64), 128>>>(z, W1 + (size_t)l * Dm * FFd, b1 + l * FFd,
                                         h1, TOK, FFd, Dm, 2);
        gemm_tf32<<<dim3(4, 64), 128>>>(h1, W2 + (size_t)l * FFd * Dm, b2 + l * Dm,
                                        f, TOK, Dm, FFd, 1);
        addln_kernel<<<TOK, 256>>>(z, f, ln2_g + l * Dm, ln2_b + l * Dm);
    }

    // encoder: exact fp32 split-K   [256,4096] @ [4096,128]
    gemm_splitk<<<dim3(2, 4, 16), 256>>>(z, ENCIN, enc_W1, 128, encpart, Np, 128, 256);
    enc_reduce<<<128, 256>>>(encpart, enc_b1, h1e);

    low_kernel<<<1, 256>>>(h1e, enc_W2, enc_b2, dec_W1, dec_b1, centers,
                           low, hd, idxp, dsq);
    recloss4<<<64, 256>>>(z, hd, dec_W2, dec_b2, recpart);
    final_kernel<<<1, 256>>>(dsq, idxp, low, recpart, (float*)d_out, out_size);
}

// round 4
// speedup vs baseline: 3.6319x; 1.6322x over previous
#include <cuda_runtime.h>
#include <math.h>

// ---------------------------------------------------------------------------
// Problem dims
// ---------------------------------------------------------------------------
#define TOK    4096
#define BATCH  8
#define SEQ    512
#define Dm     256
#define Hh     8
#define DHd    32
#define FFd    1024
#define Np     256
#define ENCIN  4096
#define Kc     5

// ---------------------------------------------------------------------------
// Scratch
// ---------------------------------------------------------------------------
__device__ float g_z [TOK * Dm];
__device__ float g_q [TOK * Dm];
__device__ float g_k [TOK * Dm];
__device__ float g_v [TOK * Dm];
__device__ float g_o [TOK * Dm];
__device__ float g_f [TOK * Dm];
__device__ float g_h1[TOK * FFd];
__device__ float g_encpart[16 * Np * 128];
__device__ float g_h1e[Np * 128];
__device__ float g_low[Np * 2];
__device__ float g_hd [Np * 128];
__device__ float g_dsq[Np];
__device__ int   g_idx[Np];
__device__ float g_recpart[Np];

// ---------------------------------------------------------------------------
__device__ __forceinline__ float blockSum256(float v) {
    __shared__ float red[8];
#pragma unroll
    for (int o = 16; o; o >>= 1) v += __shfl_xor_sync(0xffffffffu, v, o);
    if ((threadIdx.x & 31) == 0) red[threadIdx.x >> 5] = v;
    __syncthreads();
    float s = red[0] + red[1] + red[2] + red[3] + red[4] + red[5] + red[6] + red[7];
    __syncthreads();
    return s;
}

__device__ __forceinline__ void cpasync16(void* smemp, const void* g) {
    unsigned s = (unsigned)__cvta_generic_to_shared(smemp);
    asm volatile("cp.async.cg.shared.global [%0], [%1], 16;" :: "r"(s), "l"(g));
}

#define MMA_TF32(acc, afr, b0, b1)                                            \
    asm volatile(                                                             \
        "mma.sync.aligned.m16n8k8.row.col.f32.tf32.tf32.f32 "                 \
        "{%0,%1,%2,%3},{%4,%5,%6,%7},{%8,%9},{%0,%1,%2,%3};"                  \
        : "+f"((acc)[0]), "+f"((acc)[1]), "+f"((acc)[2]), "+f"((acc)[3])      \
        : "r"((afr)[0]), "r"((afr)[1]), "r"((afr)[2]), "r"((afr)[3]),         \
          "r"(b0), "r"(b1))

// ---------------------------------------------------------------------------
// Embedding
// ---------------------------------------------------------------------------
__global__ void embed_kernel(const float* __restrict__ x, const float* __restrict__ W,
                             const float* __restrict__ b, float* __restrict__ z) {
    int n = blockIdx.x, d = threadIdx.x;
    float acc = b[d];
#pragma unroll
    for (int f = 0; f < 8; f++) acc += x[n * 8 + f] * W[f * Dm + d];
    z[(size_t)n * Dm + d] = acc;
}

// ---------------------------------------------------------------------------
// Pipelined TF32 GEMM: BM=128, BN=64, BK=32, 256 thr (8 warps, 4x2 of 32x32).
// Double-buffered cp.async; raw fp32 bits into tf32 mma (HW truncation).
// Smem: As[2][128][36], Bs[2][32][72] (padded strides, 16B-aligned rows).
// ---------------------------------------------------------------------------
#define GA_STAGE (128 * 36)
#define GB_STAGE (32 * 72)
#define GEMM2_SMEM ((2 * GA_STAGE + 2 * GB_STAGE) * 4)

__device__ __forceinline__ void gemm2_body(
        const float* __restrict__ A, const float* __restrict__ B,
        const float* __restrict__ bias, float* __restrict__ C,
        int M, int N, int K, int mode) {
    extern __shared__ float smem[];
    float* As = smem;
    float* Bs = smem + 2 * GA_STAGE;

    int tid = threadIdx.x, lane = tid & 31, w = tid >> 5;
    int wr = w >> 1, wc = w & 1;
    int bm = blockIdx.y << 7, bn = blockIdx.x << 6;
    int r4 = lane >> 2, a4 = lane & 3;

    float acc[2][4][4];
#pragma unroll
    for (int mt = 0; mt < 2; mt++)
#pragma unroll
        for (int nt = 0; nt < 4; nt++)
#pragma unroll
            for (int c = 0; c < 4; c++) acc[mt][nt][c] = 0.f;

#define LOAD_STAGE(sidx, k0)                                                   \
    {                                                                          \
        float* Ad = As + (sidx) * GA_STAGE;                                    \
        float* Bd = Bs + (sidx) * GB_STAGE;                                    \
        _Pragma("unroll")                                                      \
        for (int j = 0; j < 4; j++) {                                          \
            int cA = tid + (j << 8);                                           \
            int row = cA >> 3, cc = (cA & 7) << 2;                             \
            cpasync16(&Ad[row * 36 + cc],                                      \
                      A + (size_t)(bm + row) * K + (k0) + cc);                 \
        }                                                                      \
        _Pragma("unroll")                                                      \
        for (int j = 0; j < 2; j++) {                                          \
            int cB = tid + (j << 8);                                           \
            int row = cB >> 4, cc = (cB & 15) << 2;                            \
            cpasync16(&Bd[row * 72 + cc],                                      \
                      B + (size_t)((k0) + row) * N + bn + cc);                 \
        }                                                                      \
        asm volatile("cp.async.commit_group;");                                \
    }

    int KT = K >> 5;
    LOAD_STAGE(0, 0);
    int s = 0;
    for (int kt = 0; kt < KT; kt++) {
        if (kt + 1 < KT) {
            LOAD_STAGE(s ^ 1, (kt + 1) << 5);
            asm volatile("cp.async.wait_group 1;");
        } else {
            asm volatile("cp.async.wait_group 0;");
        }
        __syncthreads();
        const float* Am = As + s * GA_STAGE;
        const float* Bm = Bs + s * GB_STAGE;
#pragma unroll
        for (int ks = 0; ks < 4; ks++) {
            int kd = (ks << 3) + a4;
            unsigned afr[2][4];
#pragma unroll
            for (int mt = 0; mt < 2; mt++) {
                int r = wr * 32 + mt * 16 + r4;
                afr[mt][0] = __float_as_uint(Am[r * 36 + kd]);
                afr[mt][1] = __float_as_uint(Am[(r + 8) * 36 + kd]);
                afr[mt][2] = __float_as_uint(Am[r * 36 + kd + 4]);
                afr[mt][3] = __float_as_uint(Am[(r + 8) * 36 + kd + 4]);
            }
#pragma unroll
            for (int nt = 0; nt < 4; nt++) {
                int n = wc * 32 + (nt << 3) + r4;
                unsigned b0 = __float_as_uint(Bm[kd * 72 + n]);
                unsigned b1 = __float_as_uint(Bm[(kd + 4) * 72 + n]);
#pragma unroll
                for (int mt = 0; mt < 2; mt++) MMA_TF32(acc[mt][nt], afr[mt], b0, b1);
            }
        }
        __syncthreads();
        s ^= 1;
    }
#undef LOAD_STAGE

#pragma unroll
    for (int mt = 0; mt < 2; mt++) {
        int row = bm + wr * 32 + mt * 16 + r4;
#pragma unroll
        for (int nt = 0; nt < 4; nt++) {
            int col = bn + wc * 32 + (nt << 3) + (a4 << 1);
            float bv0 = 0.f, bv1 = 0.f;
            if (mode >= 1) { bv0 = bias[col]; bv1 = bias[col + 1]; }
            float c0 = acc[mt][nt][0] + bv0, c1 = acc[mt][nt][1] + bv1;
            float c2 = acc[mt][nt][2] + bv0, c3 = acc[mt][nt][3] + bv1;
            if (mode == 2) {
                c0 = fmaxf(c0, 0.f); c1 = fmaxf(c1, 0.f);
                c2 = fmaxf(c2, 0.f); c3 = fmaxf(c3, 0.f);
            }
            *(float2*)(C + (size_t)row * N + col)       = make_float2(c0, c1);
            *(float2*)(C + (size_t)(row + 8) * N + col) = make_float2(c2, c3);
        }
    }
}

__global__ void __launch_bounds__(256) gemm2(
        const float* __restrict__ A, const float* __restrict__ B,
        const float* __restrict__ bias, float* __restrict__ C,
        int M, int N, int K, int mode) {
    gemm2_body(A, B, bias, C, M, N, K, mode);
}

__global__ void __launch_bounds__(256) gemm2_qkv(
        const float* __restrict__ A,
        const float* __restrict__ Wq, const float* __restrict__ Wk,
        const float* __restrict__ Wv,
        float* __restrict__ q, float* __restrict__ k, float* __restrict__ v) {
    const float* B; float* C;
    if (blockIdx.z == 0)      { B = Wq; C = q; }
    else if (blockIdx.z == 1) { B = Wk; C = k; }
    else                      { B = Wv; C = v; }
    gemm2_body(A, B, nullptr, C, TOK, Dm, Dm, 0);
}

// ---------------------------------------------------------------------------
// TF32-MMA flash attention. CTA = (qtile 64, bh), 128 threads = 4 warps.
// Each warp: 16 q-rows. Keys in 4 chunks of 128. QK^T and PV via m16n8k8.
// Smem: Qs[64][36], Ks[128][36], Vs[128][40], Ps[4][16][132].
// ---------------------------------------------------------------------------
#define AT3_SMEM_FLOATS (64 * 36 + 128 * 36 + 128 * 40 + 4 * 16 * 132)
#define AT3_SMEM_BYTES  (AT3_SMEM_FLOATS * 4)

__global__ void __launch_bounds__(128, 2) attn3(
        const float* __restrict__ qg, const float* __restrict__ kg,
        const float* __restrict__ vg, float* __restrict__ og) {
    extern __shared__ float sm[];
    float* Qs = sm;                     // [64][36] scaled
    float* Ks = Qs + 64 * 36;           // [128][36]
    float* Vs = Ks + 128 * 36;          // [128][40]
    float* Ps = Vs + 128 * 40;          // per-warp [16][132]

    int bh = blockIdx.y, b = bh >> 3, h = bh & 7;
    int qt = blockIdx.x;
    int tid = threadIdx.x, w = tid >> 5, lane = tid & 31;
    int r4 = lane >> 2, a4 = lane & 3;
    size_t base = (size_t)b * SEQ * Dm + h * DHd;
    const float scale = 0.17677669529663687f;

    // stage Q (scaled)
    for (int i = tid; i < 512; i += 128) {
        int row = i >> 3, c4 = (i & 7) << 2;
        float4 t = *(const float4*)(qg + base + (size_t)(qt * 64 + row) * Dm + c4);
        t.x *= scale; t.y *= scale; t.z *= scale; t.w *= scale;
        *(float4*)&Qs[row * 36 + c4] = t;
    }

    int q0 = w * 16;
    float* Pw = Ps + w * (16 * 132);
    float m0 = -1e30f, m1 = -1e30f, l0 = 0.f, l1 = 0.f;
    float oacc[4][4];
#pragma unroll
    for (int nt = 0; nt < 4; nt++)
#pragma unroll
        for (int c = 0; c < 4; c++) oacc[nt][c] = 0.f;

    for (int c = 0; c < 4; c++) {
        __syncthreads();
        for (int i = tid; i < 1024; i += 128) {
            int row = i >> 3, c4 = (i & 7) << 2;
            size_t goff = base + (size_t)(c * 128 + row) * Dm + c4;
            float4 tk = *(const float4*)(kg + goff);
            *(float4*)&Ks[row * 36 + c4] = tk;
            float4 tv = *(const float4*)(vg + goff);
            *(float4*)&Vs[row * 40 + c4] = tv;
        }
        __syncthreads();

        // QK^T: S[16 rows][128 keys] per warp
        float S[16][4];
#pragma unroll
        for (int nt = 0; nt < 16; nt++)
#pragma unroll
            for (int j = 0; j < 4; j++) S[nt][j] = 0.f;

#pragma unroll
        for (int ks = 0; ks < 4; ks++) {
            int kd = (ks << 3) + a4;
            unsigned aq[4];
            int r = q0 + r4;
            aq[0] = __float_as_uint(Qs[r * 36 + kd]);
            aq[1] = __float_as_uint(Qs[(r + 8) * 36 + kd]);
            aq[2] = __float_as_uint(Qs[r * 36 + kd + 4]);
            aq[3] = __float_as_uint(Qs[(r + 8) * 36 + kd + 4]);
#pragma unroll
            for (int nt = 0; nt < 16; nt++) {
                int key = (nt << 3) + r4;
                unsigned b0 = __float_as_uint(Ks[key * 36 + kd]);
                unsigned b1 = __float_as_uint(Ks[key * 36 + kd + 4]);
                MMA_TF32(S[nt], aq, b0, b1);
            }
        }

        // online softmax (rows r4 and r4+8, spread over 4-lane group)
        float mxa = -1e30f, mxb = -1e30f;
#pragma unroll
        for (int nt = 0; nt < 16; nt++) {
            mxa = fmaxf(mxa, fmaxf(S[nt][0], S[nt][1]));
            mxb = fmaxf(mxb, fmaxf(S[nt][2], S[nt][3]));
        }
#pragma unroll
        for (int off = 1; off < 4; off <<= 1) {
            mxa = fmaxf(mxa, __shfl_xor_sync(0xffffffffu, mxa, off));
            mxb = fmaxf(mxb, __shfl_xor_sync(0xffffffffu, mxb, off));
        }
        float mna = fmaxf(m0, mxa), mnb = fmaxf(m1, mxb);
        float corra = __expf(m0 - mna), corrb = __expf(m1 - mnb);
        float sa = 0.f, sb = 0.f;
#pragma unroll
        for (int nt = 0; nt < 16; nt++) {
            float p0 = __expf(S[nt][0] - mna);
            float p1 = __expf(S[nt][1] - mna);
            float p2 = __expf(S[nt][2] - mnb);
            float p3 = __expf(S[nt][3] - mnb);
            sa += p0 + p1; sb += p2 + p3;
            int col = (nt << 3) + (a4 << 1);
            *(float2*)&Pw[r4 * 132 + col]       = make_float2(p0, p1);
            *(float2*)&Pw[(r4 + 8) * 132 + col] = make_float2(p2, p3);
        }
#pragma unroll
        for (int off = 1; off < 4; off <<= 1) {
            sa += __shfl_xor_sync(0xffffffffu, sa, off);
            sb += __shfl_xor_sync(0xffffffffu, sb, off);
        }
        l0 = l0 * corra + sa; m0 = mna;
        l1 = l1 * corrb + sb; m1 = mnb;
#pragma unroll
        for (int nt = 0; nt < 4; nt++) {
            oacc[nt][0] *= corra; oacc[nt][1] *= corra;
            oacc[nt][2] *= corrb; oacc[nt][3] *= corrb;
        }
        __syncwarp();

        // PV: O[16][32] += P[16][128] @ V[128][32]
#pragma unroll
        for (int ks = 0; ks < 16; ks++) {
            int key = (ks << 3) + a4;
            unsigned ap[4];
            ap[0] = __float_as_uint(Pw[r4 * 132 + key]);
            ap[1] = __float_as_uint(Pw[(r4 + 8) * 132 + key]);
            ap[2] = __float_as_uint(Pw[r4 * 132 + key + 4]);
            ap[3] = __float_as_uint(Pw[(r4 + 8) * 132 + key + 4]);
#pragma unroll
            for (int nt = 0; nt < 4; nt++) {
                int dim = (nt << 3) + r4;
                unsigned b0 = __float_as_uint(Vs[key * 40 + dim]);
                unsigned b1 = __float_as_uint(Vs[(key + 4) * 40 + dim]);
                MMA_TF32(oacc[nt], ap, b0, b1);
            }
        }
    }

    float inva = 1.f / l0, invb = 1.f / l1;
    int rowa = qt * 64 + q0 + r4;
#pragma unroll
    for (int nt = 0; nt < 4; nt++) {
        int col = (nt << 3) + (a4 << 1);
        *(float2*)(og + base + (size_t)rowa * Dm + col) =
            make_float2(oacc[nt][0] * inva, oacc[nt][1] * inva);
        *(float2*)(og + base + (size_t)(rowa + 8) * Dm + col) =
            make_float2(oacc[nt][2] * invb, oacc[nt][3] * invb);
    }
}

// ---------------------------------------------------------------------------
// fp32 split-K GEMM (encoder path — exact)
// ---------------------------------------------------------------------------
__global__ void __launch_bounds__(256) gemm_splitk(
        const float* __restrict__ A, int lda, const float* __restrict__ B, int ldb,
        float* __restrict__ Cp, int M, int N, int Kchunk) {
    __shared__ float As[16][65];
    __shared__ float Bs[16][64];
    int zc = blockIdx.z;
    A  += zc * Kchunk;
    B  += (size_t)zc * Kchunk * ldb;
    Cp += (size_t)zc * M * N;
    int tid = threadIdx.x;
    int bm = blockIdx.y << 6, bn = blockIdx.x << 6;
    int tx = tid & 15, ty = tid >> 4;
    int arow = tid >> 2, acol = (tid & 3) << 2;
    int brow = tid >> 4, bcol = (tid & 15) << 2;

    float acc[4][4] = {};
    for (int k0 = 0; k0 < Kchunk; k0 += 16) {
        float4 a4 = *(const float4*)(A + (size_t)(bm + arow) * lda + k0 + acol);
        As[acol + 0][arow] = a4.x; As[acol + 1][arow] = a4.y;
        As[acol + 2][arow] = a4.z; As[acol + 3][arow] = a4.w;
        float4 b4 = *(const float4*)(B + (size_t)(k0 + brow) * ldb + bn + bcol);
        *(float4*)&Bs[brow][bcol] = b4;
        __syncthreads();
#pragma unroll
        for (int kk = 0; kk < 16; kk++) {
            float a0 = As[kk][(ty << 2) + 0], a1 = As[kk][(ty << 2) + 1];
            float a2 = As[kk][(ty << 2) + 2], a3 = As[kk][(ty << 2) + 3];
            float4 b = *(const float4*)&Bs[kk][tx << 2];
            acc[0][0] += a0 * b.x; acc[0][1] += a0 * b.y; acc[0][2] += a0 * b.z; acc[0][3] += a0 * b.w;
            acc[1][0] += a1 * b.x; acc[1][1] += a1 * b.y; acc[1][2] += a1 * b.z; acc[1][3] += a1 * b.w;
            acc[2][0] += a2 * b.x; acc[2][1] += a2 * b.y; acc[2][2] += a2 * b.z; acc[2][3] += a2 * b.w;
            acc[3][0] += a3 * b.x; acc[3][1] += a3 * b.y; acc[3][2] += a3 * b.z; acc[3][3] += a3 * b.w;
        }
        __syncthreads();
    }
#pragma unroll
    for (int i = 0; i < 4; i++) {
        float4 r = make_float4(acc[i][0], acc[i][1], acc[i][2], acc[i][3]);
        *(float4*)(Cp + (size_t)(bm + (ty << 2) + i) * N + bn + (tx << 2)) = r;
    }
}

__global__ void enc_reduce(const float* __restrict__ part, const float* __restrict__ bias,
                           float* __restrict__ out) {
    int i = blockIdx.x * 256 + threadIdx.x;
    float s = bias[i & 127];
#pragma unroll
    for (int c = 0; c < 16; c++) s += part[c * (Np * 128) + i];
    out[i] = fmaxf(s, 0.f);
}

// ---------------------------------------------------------------------------
// Residual + LayerNorm
// ---------------------------------------------------------------------------
__global__ void addln_kernel(float* __restrict__ z, const float* __restrict__ delta,
                             const float* __restrict__ gam, const float* __restrict__ bet) {
    int row = blockIdx.x, tid = threadIdx.x;
    size_t off = (size_t)row * Dm + tid;
    float vv = z[off] + delta[off];
    float mu = blockSum256(vv) * (1.f / 256.f);
    float dv = vv - mu;
    float var = blockSum256(dv * dv) * (1.f / 256.f);
    z[off] = dv * rsqrtf(var + 1e-5f) * gam[tid] + bet[tid];
}

// ---------------------------------------------------------------------------
// Encoder head + decoder hidden + assignment (exact fp32)
// ---------------------------------------------------------------------------
__global__ void low_kernel(const float* __restrict__ h1e, const float* __restrict__ eW2,
                           const float* __restrict__ eb2, const float* __restrict__ dW1,
                           const float* __restrict__ db1, const float* __restrict__ ctr,
                           float* __restrict__ low, float* __restrict__ hd,
                           int* __restrict__ idxp, float* __restrict__ dsq) {
    __shared__ float w2[256], dw[256], db[128], cc[10];
    int n = threadIdx.x;
    w2[n] = eW2[n];
    dw[n] = dW1[n];
    if (n < 128) db[n] = db1[n];
    if (n < 10)  cc[n] = ctr[n];
    __syncthreads();

    float a0 = eb2[0], a1 = eb2[1];
    for (int kk = 0; kk < 128; kk++) {
        float hv = h1e[n * 128 + kk];
        a0 += hv * w2[kk * 2 + 0];
        a1 += hv * w2[kk * 2 + 1];
    }
    float l0 = 1.f / (1.f + expf(-a0));
    float l1 = 1.f / (1.f + expf(-a1));
    low[n * 2 + 0] = l0;
    low[n * 2 + 1] = l1;
    for (int mm = 0; mm < 128; mm++) {
        float hv = l0 * dw[mm] + l1 * dw[128 + mm] + db[mm];
        hd[n * 128 + mm] = fmaxf(hv, 0.f);
    }
    int best = 0; float bd = 3.4e38f;
#pragma unroll
    for (int c = 0; c < Kc; c++) {
        float dx = l0 - cc[2 * c], dy = l1 - cc[2 * c + 1];
        float d2 = dx * dx + dy * dy;
        if (d2 < bd) { bd = d2; best = c; }
    }
    idxp[n] = best;
    dsq[n] = bd;
}

// ---------------------------------------------------------------------------
// Reconstruction L1: 4 points per CTA
// ---------------------------------------------------------------------------
__global__ void __launch_bounds__(256) recloss4(
        const float* __restrict__ pts, const float* __restrict__ hd,
        const float* __restrict__ W2, const float* __restrict__ b2,
        float* __restrict__ part) {
    int n0 = blockIdx.x * 4, tid = threadIdx.x;
    __shared__ float hs[4][128];
    for (int i = tid; i < 512; i += 256) hs[i >> 7][i & 127] = hd[n0 * 128 + i];
    __syncthreads();
    float acc0 = 0.f, acc1 = 0.f, acc2 = 0.f, acc3 = 0.f;
    for (int f = tid; f < ENCIN; f += 256) {
        float bb = b2[f];
        float r0 = bb, r1 = bb, r2 = bb, r3 = bb;
#pragma unroll 4
        for (int kk = 0; kk < 128; kk += 4) {
#pragma unroll
            for (int j = 0; j < 4; j++) {
                float wv = W2[(size_t)(kk + j) * ENCIN + f];
                r0 += hs[0][kk + j] * wv;
                r1 += hs[1][kk + j] * wv;
                r2 += hs[2][kk + j] * wv;
                r3 += hs[3][kk + j] * wv;
            }
        }
        acc0 += fabsf(pts[(size_t)(n0 + 0) * ENCIN + f] - r0);
        acc1 += fabsf(pts[(size_t)(n0 + 1) * ENCIN + f] - r1);
        acc2 += fabsf(pts[(size_t)(n0 + 2) * ENCIN + f] - r2);
        acc3 += fabsf(pts[(size_t)(n0 + 3) * ENCIN + f] - r3);
    }
    float s0 = blockSum256(acc0);
    float s1 = blockSum256(acc1);
    float s2 = blockSum256(acc2);
    float s3 = blockSum256(acc3);
    if (tid == 0) { part[n0] = s0; part[n0 + 1] = s1; part[n0 + 2] = s2; part[n0 + 3] = s3; }
}

// ---------------------------------------------------------------------------
// Final losses + output
// ---------------------------------------------------------------------------
__global__ void final_kernel(const float* __restrict__ dsq, const int* __restrict__ idxp,
                             const float* __restrict__ low, const float* __restrict__ recpart,
                             float* __restrict__ out, int out_size) {
    __shared__ float sums[Kc], cnts[Kc];
    int tid = threadIdx.x;
    float d = dsq[tid];
    int my = idxp[tid];

    float inter = blockSum256(d) * (1.f / 256.f);

    if (tid < Kc) { sums[tid] = 0.f; cnts[tid] = 0.f; }
    __syncthreads();
    atomicAdd(&sums[my], d);
    atomicAdd(&cnts[my], 1.f);
    __syncthreads();

    bool mem = false;
    for (int j = 0; j < 256; j++) {
        if (idxp[j] == tid) { mem = true; break; }
    }
    float arr = mem ? 100.f : 0.f;

    float se = blockSum256(expf(arr - 100.f));
    float lse = logf(se) + 100.f;
    float logp = arr - lse;

    float klsum = blockSum256(-logf(256.f) - logp);
    float kl = klsum * (1.f / (256.f * 256.f));

    float rec = blockSum256(recpart[tid]) * (1.f / (256.f * 4096.f));

    if (tid == 0) {
        float intra = 0.f, ne = 0.f;
#pragma unroll
        for (int c = 0; c < Kc; c++) {
            if (cnts[c] > 0.f) { intra += sums[c] / fmaxf(cnts[c], 1.f); ne += 1.f; }
        }
        intra /= fmaxf(ne, 1.f);
        float loss = inter + intra + kl + rec;
        if (out_size > 0) out[0] = loss;
        if (out_size > 1) out[1] = kl;
    }
    if (2 + tid < out_size) out[2 + tid] = (float)my;
    int p0 = 258 + 2 * tid;
    if (p0 < out_size)     out[p0]     = low[2 * tid];
    if (p0 + 1 < out_size) out[p0 + 1] = low[2 * tid + 1];
}

// ---------------------------------------------------------------------------
// Host launcher
// ---------------------------------------------------------------------------
extern "C" void kernel_launch(void* const* d_in, const int* in_sizes, int n_in,
                              void* d_out, int out_size) {
    const float* x_seg  = (const float*)d_in[1];
    const float* emb_W  = (const float*)d_in[2];
    const float* emb_b  = (const float*)d_in[3];
    const float* Wq     = (const float*)d_in[4];
    const float* Wk     = (const float*)d_in[5];
    const float* Wv     = (const float*)d_in[6];
    const float* Wo     = (const float*)d_in[7];
    const float* W1     = (const float*)d_in[8];
    const float* b1     = (const float*)d_in[9];
    const float* W2     = (const float*)d_in[10];
    const float* b2     = (const float*)d_in[11];
    const float* ln1_g  = (const float*)d_in[12];
    const float* ln1_b  = (const float*)d_in[13];
    const float* ln2_g  = (const float*)d_in[14];
    const float* ln2_b  = (const float*)d_in[15];
    const float* enc_W1 = (const float*)d_in[16];
    const float* enc_b1 = (const float*)d_in[17];
    const float* enc_W2 = (const float*)d_in[18];
    const float* enc_b2 = (const float*)d_in[19];
    const float* dec_W1 = (const float*)d_in[20];
    const float* dec_b1 = (const float*)d_in[21];
    const float* dec_W2 = (const float*)d_in[22];
    const float* dec_b2 = (const float*)d_in[23];
    const float* centers = (const float*)d_in[24];

    float *z, *q, *k, *v, *o, *f, *h1, *encpart, *h1e, *low, *hd, *dsq, *recpart;
    int* idxp;
    cudaGetSymbolAddress((void**)&z,   g_z);
    cudaGetSymbolAddress((void**)&q,   g_q);
    cudaGetSymbolAddress((void**)&k,   g_k);
    cudaGetSymbolAddress((void**)&v,   g_v);
    cudaGetSymbolAddress((void**)&o,   g_o);
    cudaGetSymbolAddress((void**)&f,   g_f);
    cudaGetSymbolAddress((void**)&h1,  g_h1);
    cudaGetSymbolAddress((void**)&encpart, g_encpart);
    cudaGetSymbolAddress((void**)&h1e, g_h1e);
    cudaGetSymbolAddress((void**)&low, g_low);
    cudaGetSymbolAddress((void**)&hd,  g_hd);
    cudaGetSymbolAddress((void**)&dsq, g_dsq);
    cudaGetSymbolAddress((void**)&idxp, g_idx);
    cudaGetSymbolAddress((void**)&recpart, g_recpart);

    cudaFuncSetAttribute(gemm2,     cudaFuncAttributeMaxDynamicSharedMemorySize, GEMM2_SMEM);
    cudaFuncSetAttribute(gemm2_qkv, cudaFuncAttributeMaxDynamicSharedMemorySize, GEMM2_SMEM);
    cudaFuncSetAttribute(attn3,     cudaFuncAttributeMaxDynamicSharedMemorySize, AT3_SMEM_BYTES);

    embed_kernel<<<TOK, 256>>>(x_seg, emb_W, emb_b, z);

    for (int l = 0; l < 2; l++) {
        size_t wo = (size_t)l * Dm * Dm;
        gemm2_qkv<<<dim3(4, 32, 3), 256, GEMM2_SMEM>>>(z, Wq + wo, Wk + wo, Wv + wo, q, k, v);
        attn3<<<dim3(8, 64), 128, AT3_SMEM_BYTES>>>(q, k, v, o);
        gemm2<<<dim3(4, 32), 256, GEMM2_SMEM>>>(o, Wo + wo, nullptr, q, TOK, Dm, Dm, 0);
        addln_kernel<<<TOK, 256>>>(z, q, ln1_g + l * Dm, ln1_b + l * Dm);
        gemm2<<<dim3(16, 32), 256, GEMM2_SMEM>>>(z, W1 + (size_t)l * Dm * FFd, b1 + l * FFd,
                                                 h1, TOK, FFd, Dm, 2);
        gemm2<<<dim3(4, 32), 256, GEMM2_SMEM>>>(h1, W2 + (size_t)l * FFd * Dm, b2 + l * Dm,
                                                f, TOK, Dm, FFd, 1);
        addln_kernel<<<TOK, 256>>>(z, f, ln2_g + l * Dm, ln2_b + l * Dm);
    }

    gemm_splitk<<<dim3(2, 4, 16), 256>>>(z, ENCIN, enc_W1, 128, encpart, Np, 128, 256);
    enc_reduce<<<128, 256>>>(encpart, enc_b1, h1e);

    low_kernel<<<1, 256>>>(h1e, enc_W2, enc_b2, dec_W1, dec_b1, centers,
                           low, hd, idxp, dsq);
    recloss4<<<64, 256>>>(z, hd, dec_W2, dec_b2, recpart);
    final_kernel<<<1, 256>>>(dsq, idxp, low, recpart, (float*)d_out, out_size);
}

// round 5
// speedup vs baseline: 4.9157x; 1.3535x over previous
#include <cuda_runtime.h>
#include <math.h>

// ---------------------------------------------------------------------------
// Problem dims
// ---------------------------------------------------------------------------
#define TOK    4096
#define BATCH  8
#define SEQ    512
#define Dm     256
#define Hh     8
#define DHd    32
#define FFd    1024
#define Np     256
#define ENCIN  4096
#define Kc     5

// ---------------------------------------------------------------------------
// Scratch
// ---------------------------------------------------------------------------
__device__ float g_z [TOK * Dm];
__device__ float g_q [TOK * Dm];
__device__ float g_k [TOK * Dm];
__device__ float g_v [TOK * Dm];
__device__ float g_o [TOK * Dm];
__device__ float g_f [TOK * Dm];
__device__ float g_h1[TOK * FFd];
__device__ float g_encpart[32 * Np * 128];
__device__ float g_h1e[Np * 128];
__device__ float g_low[Np * 2];
__device__ float g_hd [Np * 128];
__device__ float g_dsq[Np];
__device__ int   g_idx[Np];
__device__ float g_recpart[Np];   // 256 CTA partials from recgemm

// ---------------------------------------------------------------------------
__device__ __forceinline__ float blockSum256(float v) {
    __shared__ float red[8];
#pragma unroll
    for (int o = 16; o; o >>= 1) v += __shfl_xor_sync(0xffffffffu, v, o);
    if ((threadIdx.x & 31) == 0) red[threadIdx.x >> 5] = v;
    __syncthreads();
    float s = red[0] + red[1] + red[2] + red[3] + red[4] + red[5] + red[6] + red[7];
    __syncthreads();
    return s;
}

__device__ __forceinline__ float blockSum128(float v) {
    __shared__ float red[4];
#pragma unroll
    for (int o = 16; o; o >>= 1) v += __shfl_xor_sync(0xffffffffu, v, o);
    if ((threadIdx.x & 31) == 0) red[threadIdx.x >> 5] = v;
    __syncthreads();
    float s = red[0] + red[1] + red[2] + red[3];
    __syncthreads();
    return s;
}

__device__ __forceinline__ void cpasync16(void* smemp, const void* g) {
    unsigned s = (unsigned)__cvta_generic_to_shared(smemp);
    asm volatile("cp.async.cg.shared.global [%0], [%1], 16;" :: "r"(s), "l"(g));
}

#define MMA_TF32(acc, afr, b0, b1)                                            \
    asm volatile(                                                             \
        "mma.sync.aligned.m16n8k8.row.col.f32.tf32.tf32.f32 "                 \
        "{%0,%1,%2,%3},{%4,%5,%6,%7},{%8,%9},{%0,%1,%2,%3};"                  \
        : "+f"((acc)[0]), "+f"((acc)[1]), "+f"((acc)[2]), "+f"((acc)[3])      \
        : "r"((afr)[0]), "r"((afr)[1]), "r"((afr)[2]), "r"((afr)[3]),         \
          "r"(b0), "r"(b1))

// ---------------------------------------------------------------------------
// Embedding
// ---------------------------------------------------------------------------
__global__ void embed_kernel(const float* __restrict__ x, const float* __restrict__ W,
                             const float* __restrict__ b, float* __restrict__ z) {
    int n = blockIdx.x, d = threadIdx.x;
    float acc = b[d];
#pragma unroll
    for (int f = 0; f < 8; f++) acc += x[n * 8 + f] * W[f * Dm + d];
    z[(size_t)n * Dm + d] = acc;
}

// ---------------------------------------------------------------------------
// TF32 GEMM core: BM=BN=64, BK=32, 128 threads (4 warps, 2x2 of 32x32),
// 3-stage cp.async pipeline, raw fp32 bits into tf32 mma.
// Smem/stage: A[64][36] + B[32][72].
// ---------------------------------------------------------------------------
#define G3_A (64 * 36)
#define G3_B (32 * 72)
#define G3_STAGE (G3_A + G3_B)
#define GEMM3_SMEM (3 * G3_STAGE * 4)

__device__ __forceinline__ void gemm3_core(
        const float* __restrict__ A, const float* __restrict__ B,
        int N, int K, int bm, int bn, float acc[2][4][4]) {
    extern __shared__ float smem[];
    int tid = threadIdx.x, lane = tid & 31, w = tid >> 5;
    int wr = w >> 1, wc = w & 1;
    int r4 = lane >> 2, a4 = lane & 3;

#pragma unroll
    for (int mt = 0; mt < 2; mt++)
#pragma unroll
        for (int nt = 0; nt < 4; nt++)
#pragma unroll
            for (int c = 0; c < 4; c++) acc[mt][nt][c] = 0.f;

#define G3_LOAD(sidx, k0)                                                     \
    {                                                                         \
        float* Ad = smem + (sidx) * G3_STAGE;                                 \
        float* Bd = Ad + G3_A;                                                \
        _Pragma("unroll")                                                     \
        for (int j = 0; j < 4; j++) {                                         \
            int idx = tid + (j << 7);                                         \
            int row = idx >> 3, cc = (idx & 7) << 2;                          \
            cpasync16(&Ad[row * 36 + cc],                                     \
                      A + (size_t)(bm + row) * K + (k0) + cc);                \
        }                                                                     \
        _Pragma("unroll")                                                     \
        for (int j = 0; j < 4; j++) {                                         \
            int idx = tid + (j << 7);                                         \
            int row = idx >> 4, cc = (idx & 15) << 2;                         \
            cpasync16(&Bd[row * 72 + cc],                                     \
                      B + (size_t)((k0) + row) * N + bn + cc);                \
        }                                                                     \
        asm volatile("cp.async.commit_group;");                               \
    }

    int KT = K >> 5;
    G3_LOAD(0, 0);
    if (KT > 1) G3_LOAD(1, 32);

    int s = 0;
    for (int kt = 0; kt < KT; kt++) {
        if (kt + 1 < KT) asm volatile("cp.async.wait_group 1;");
        else             asm volatile("cp.async.wait_group 0;");
        __syncthreads();
        if (kt + 2 < KT) {
            int sn = s + 2; if (sn >= 3) sn -= 3;
            G3_LOAD(sn, (kt + 2) << 5);
        }
        const float* Am = smem + s * G3_STAGE;
        const float* Bm = Am + G3_A;
#pragma unroll
        for (int ks = 0; ks < 4; ks++) {
            int kd = (ks << 3) + a4;
            unsigned afr[2][4];
#pragma unroll
            for (int mt = 0; mt < 2; mt++) {
                int r = wr * 32 + mt * 16 + r4;
                afr[mt][0] = __float_as_uint(Am[r * 36 + kd]);
                afr[mt][1] = __float_as_uint(Am[(r + 8) * 36 + kd]);
                afr[mt][2] = __float_as_uint(Am[r * 36 + kd + 4]);
                afr[mt][3] = __float_as_uint(Am[(r + 8) * 36 + kd + 4]);
            }
#pragma unroll
            for (int nt = 0; nt < 4; nt++) {
                int n = wc * 32 + (nt << 3) + r4;
                unsigned b0 = __float_as_uint(Bm[kd * 72 + n]);
                unsigned b1 = __float_as_uint(Bm[(kd + 4) * 72 + n]);
#pragma unroll
                for (int mt = 0; mt < 2; mt++) MMA_TF32(acc[mt][nt], afr[mt], b0, b1);
            }
        }
        __syncthreads();
        s++; if (s >= 3) s -= 3;
    }
#undef G3_LOAD
}

// Standard epilogue: (+bias)(+relu), write C
__device__ __forceinline__ void gemm3_store(
        float acc[2][4][4], const float* __restrict__ bias, float* __restrict__ C,
        int N, int bm, int bn, int mode) {
    int tid = threadIdx.x, lane = tid & 31, w = tid >> 5;
    int wr = w >> 1, wc = w & 1;
    int r4 = lane >> 2, a4 = lane & 3;
#pragma unroll
    for (int mt = 0; mt < 2; mt++) {
        int row = bm + wr * 32 + mt * 16 + r4;
#pragma unroll
        for (int nt = 0; nt < 4; nt++) {
            int col = bn + wc * 32 + (nt << 3) + (a4 << 1);
            float bv0 = 0.f, bv1 = 0.f;
            if (mode >= 1) { bv0 = bias[col]; bv1 = bias[col + 1]; }
            float c0 = acc[mt][nt][0] + bv0, c1 = acc[mt][nt][1] + bv1;
            float c2 = acc[mt][nt][2] + bv0, c3 = acc[mt][nt][3] + bv1;
            if (mode == 2) {
                c0 = fmaxf(c0, 0.f); c1 = fmaxf(c1, 0.f);
                c2 = fmaxf(c2, 0.f); c3 = fmaxf(c3, 0.f);
            }
            *(float2*)(C + (size_t)row * N + col)       = make_float2(c0, c1);
            *(float2*)(C + (size_t)(row + 8) * N + col) = make_float2(c2, c3);
        }
    }
}

__global__ void __launch_bounds__(128) gemm3(
        const float* __restrict__ A, const float* __restrict__ B,
        const float* __restrict__ bias, float* __restrict__ C,
        int M, int N, int K, int mode) {
    float acc[2][4][4];
    int bm = blockIdx.y << 6, bn = blockIdx.x << 6;
    gemm3_core(A, B, N, K, bm, bn, acc);
    gemm3_store(acc, bias, C, N, bm, bn, mode);
}

__global__ void __launch_bounds__(128) gemm3_qkv(
        const float* __restrict__ A,
        const float* __restrict__ Wq, const float* __restrict__ Wk,
        const float* __restrict__ Wv,
        float* __restrict__ q, float* __restrict__ k, float* __restrict__ v) {
    const float* B; float* C;
    if (blockIdx.z == 0)      { B = Wq; C = q; }
    else if (blockIdx.z == 1) { B = Wk; C = k; }
    else                      { B = Wv; C = v; }
    float acc[2][4][4];
    int bm = blockIdx.y << 6, bn = blockIdx.x << 6;
    gemm3_core(A, B, Dm, Dm, bm, bn, acc);
    gemm3_store(acc, nullptr, C, Dm, bm, bn, 0);
}

// ---------------------------------------------------------------------------
// Reconstruction loss GEMM: rec = hd[256,128] @ dec_W2[128,4096] + b2,
// epilogue accumulates |pts - rec| into one partial per CTA. Grid (64,4).
// ---------------------------------------------------------------------------
__global__ void __launch_bounds__(128) recgemm(
        const float* __restrict__ hd, const float* __restrict__ W2,
        const float* __restrict__ b2, const float* __restrict__ pts,
        float* __restrict__ part) {
    float acc[2][4][4];
    int bm = blockIdx.y << 6, bn = blockIdx.x << 6;
    gemm3_core(hd, W2, ENCIN, 128, bm, bn, acc);

    int tid = threadIdx.x, lane = tid & 31, w = tid >> 5;
    int wr = w >> 1, wc = w & 1;
    int r4 = lane >> 2, a4 = lane & 3;
    float local = 0.f;
#pragma unroll
    for (int mt = 0; mt < 2; mt++) {
        int row = bm + wr * 32 + mt * 16 + r4;
#pragma unroll
        for (int nt = 0; nt < 4; nt++) {
            int col = bn + wc * 32 + (nt << 3) + (a4 << 1);
            float bv0 = b2[col], bv1 = b2[col + 1];
            float2 p0 = *(const float2*)(pts + (size_t)row * ENCIN + col);
            float2 p1 = *(const float2*)(pts + (size_t)(row + 8) * ENCIN + col);
            local += fabsf(p0.x - (acc[mt][nt][0] + bv0));
            local += fabsf(p0.y - (acc[mt][nt][1] + bv1));
            local += fabsf(p1.x - (acc[mt][nt][2] + bv0));
            local += fabsf(p1.y - (acc[mt][nt][3] + bv1));
        }
    }
    float s = blockSum128(local);
    if (tid == 0) part[blockIdx.y * gridDim.x + blockIdx.x] = s;
}

// ---------------------------------------------------------------------------
// TF32-MMA flash attention (unchanged from R4)
// ---------------------------------------------------------------------------
#define AT3_SMEM_FLOATS (64 * 36 + 128 * 36 + 128 * 40 + 4 * 16 * 132)
#define AT3_SMEM_BYTES  (AT3_SMEM_FLOATS * 4)

__global__ void __launch_bounds__(128, 2) attn3(
        const float* __restrict__ qg, const float* __restrict__ kg,
        const float* __restrict__ vg, float* __restrict__ og) {
    extern __shared__ float sm[];
    float* Qs = sm;
    float* Ks = Qs + 64 * 36;
    float* Vs = Ks + 128 * 36;
    float* Ps = Vs + 128 * 40;

    int bh = blockIdx.y, b = bh >> 3, h = bh & 7;
    int qt = blockIdx.x;
    int tid = threadIdx.x, w = tid >> 5, lane = tid & 31;
    int r4 = lane >> 2, a4 = lane & 3;
    size_t base = (size_t)b * SEQ * Dm + h * DHd;
    const float scale = 0.17677669529663687f;

    for (int i = tid; i < 512; i += 128) {
        int row = i >> 3, c4 = (i & 7) << 2;
        float4 t = *(const float4*)(qg + base + (size_t)(qt * 64 + row) * Dm + c4);
        t.x *= scale; t.y *= scale; t.z *= scale; t.w *= scale;
        *(float4*)&Qs[row * 36 + c4] = t;
    }

    int q0 = w * 16;
    float* Pw = Ps + w * (16 * 132);
    float m0 = -1e30f, m1 = -1e30f, l0 = 0.f, l1 = 0.f;
    float oacc[4][4];
#pragma unroll
    for (int nt = 0; nt < 4; nt++)
#pragma unroll
        for (int c = 0; c < 4; c++) oacc[nt][c] = 0.f;

    for (int c = 0; c < 4; c++) {
        __syncthreads();
        for (int i = tid; i < 1024; i += 128) {
            int row = i >> 3, c4 = (i & 7) << 2;
            size_t goff = base + (size_t)(c * 128 + row) * Dm + c4;
            float4 tk = *(const float4*)(kg + goff);
            *(float4*)&Ks[row * 36 + c4] = tk;
            float4 tv = *(const float4*)(vg + goff);
            *(float4*)&Vs[row * 40 + c4] = tv;
        }
        __syncthreads();

        float S[16][4];
#pragma unroll
        for (int nt = 0; nt < 16; nt++)
#pragma unroll
            for (int j = 0; j < 4; j++) S[nt][j] = 0.f;

#pragma unroll
        for (int ks = 0; ks < 4; ks++) {
            int kd = (ks << 3) + a4;
            unsigned aq[4];
            int r = q0 + r4;
            aq[0] = __float_as_uint(Qs[r * 36 + kd]);
            aq[1] = __float_as_uint(Qs[(r + 8) * 36 + kd]);
            aq[2] = __float_as_uint(Qs[r * 36 + kd + 4]);
            aq[3] = __float_as_uint(Qs[(r + 8) * 36 + kd + 4]);
#pragma unroll
            for (int nt = 0; nt < 16; nt++) {
                int key = (nt << 3) + r4;
                unsigned b0 = __float_as_uint(Ks[key * 36 + kd]);
                unsigned b1 = __float_as_uint(Ks[key * 36 + kd + 4]);
                MMA_TF32(S[nt], aq, b0, b1);
            }
        }

        float mxa = -1e30f, mxb = -1e30f;
#pragma unroll
        for (int nt = 0; nt < 16; nt++) {
            mxa = fmaxf(mxa, fmaxf(S[nt][0], S[nt][1]));
            mxb = fmaxf(mxb, fmaxf(S[nt][2], S[nt][3]));
        }
#pragma unroll
        for (int off = 1; off < 4; off <<= 1) {
            mxa = fmaxf(mxa, __shfl_xor_sync(0xffffffffu, mxa, off));
            mxb = fmaxf(mxb, __shfl_xor_sync(0xffffffffu, mxb, off));
        }
        float mna = fmaxf(m0, mxa), mnb = fmaxf(m1, mxb);
        float corra = __expf(m0 - mna), corrb = __expf(m1 - mnb);
        float sa = 0.f, sb = 0.f;
#pragma unroll
        for (int nt = 0; nt < 16; nt++) {
            float p0 = __expf(S[nt][0] - mna);
            float p1 = __expf(S[nt][1] - mna);
            float p2 = __expf(S[nt][2] - mnb);
            float p3 = __expf(S[nt][3] - mnb);
            sa += p0 + p1; sb += p2 + p3;
            int col = (nt << 3) + (a4 << 1);
            *(float2*)&Pw[r4 * 132 + col]       = make_float2(p0, p1);
            *(float2*)&Pw[(r4 + 8) * 132 + col] = make_float2(p2, p3);
        }
#pragma unroll
        for (int off = 1; off < 4; off <<= 1) {
            sa += __shfl_xor_sync(0xffffffffu, sa, off);
            sb += __shfl_xor_sync(0xffffffffu, sb, off);
        }
        l0 = l0 * corra + sa; m0 = mna;
        l1 = l1 * corrb + sb; m1 = mnb;
#pragma unroll
        for (int nt = 0; nt < 4; nt++) {
            oacc[nt][0] *= corra; oacc[nt][1] *= corra;
            oacc[nt][2] *= corrb; oacc[nt][3] *= corrb;
        }
        __syncwarp();

#pragma unroll
        for (int ks = 0; ks < 16; ks++) {
            int key = (ks << 3) + a4;
            unsigned ap[4];
            ap[0] = __float_as_uint(Pw[r4 * 132 + key]);
            ap[1] = __float_as_uint(Pw[(r4 + 8) * 132 + key]);
            ap[2] = __float_as_uint(Pw[r4 * 132 + key + 4]);
            ap[3] = __float_as_uint(Pw[(r4 + 8) * 132 + key + 4]);
#pragma unroll
            for (int nt = 0; nt < 4; nt++) {
                int dim = (nt << 3) + r4;
                unsigned b0 = __float_as_uint(Vs[key * 40 + dim]);
                unsigned b1 = __float_as_uint(Vs[(key + 4) * 40 + dim]);
                MMA_TF32(oacc[nt], ap, b0, b1);
            }
        }
    }

    float inva = 1.f / l0, invb = 1.f / l1;
    int rowa = qt * 64 + q0 + r4;
#pragma unroll
    for (int nt = 0; nt < 4; nt++) {
        int col = (nt << 3) + (a4 << 1);
        *(float2*)(og + base + (size_t)rowa * Dm + col) =
            make_float2(oacc[nt][0] * inva, oacc[nt][1] * inva);
        *(float2*)(og + base + (size_t)(rowa + 8) * Dm + col) =
            make_float2(oacc[nt][2] * invb, oacc[nt][3] * invb);
    }
}

// ---------------------------------------------------------------------------
// fp32 split-K GEMM (encoder path — exact). Kchunk=128, grid (2,4,32).
// ---------------------------------------------------------------------------
__global__ void __launch_bounds__(256) gemm_splitk(
        const float* __restrict__ A, int lda, const float* __restrict__ B, int ldb,
        float* __restrict__ Cp, int M, int N, int Kchunk) {
    __shared__ float As[16][65];
    __shared__ float Bs[16][64];
    int zc = blockIdx.z;
    A  += zc * Kchunk;
    B  += (size_t)zc * Kchunk * ldb;
    Cp += (size_t)zc * M * N;
    int tid = threadIdx.x;
    int bm = blockIdx.y << 6, bn = blockIdx.x << 6;
    int tx = tid & 15, ty = tid >> 4;
    int arow = tid >> 2, acol = (tid & 3) << 2;
    int brow = tid >> 4, bcol = (tid & 15) << 2;

    float acc[4][4] = {};
    for (int k0 = 0; k0 < Kchunk; k0 += 16) {
        float4 a4 = *(const float4*)(A + (size_t)(bm + arow) * lda + k0 + acol);
        As[acol + 0][arow] = a4.x; As[acol + 1][arow] = a4.y;
        As[acol + 2][arow] = a4.z; As[acol + 3][arow] = a4.w;
        float4 b4 = *(const float4*)(B + (size_t)(k0 + brow) * ldb + bn + bcol);
        *(float4*)&Bs[brow][bcol] = b4;
        __syncthreads();
#pragma unroll
        for (int kk = 0; kk < 16; kk++) {
            float a0 = As[kk][(ty << 2) + 0], a1 = As[kk][(ty << 2) + 1];
            float a2 = As[kk][(ty << 2) + 2], a3 = As[kk][(ty << 2) + 3];
            float4 b = *(const float4*)&Bs[kk][tx << 2];
            acc[0][0] += a0 * b.x; acc[0][1] += a0 * b.y; acc[0][2] += a0 * b.z; acc[0][3] += a0 * b.w;
            acc[1][0] += a1 * b.x; acc[1][1] += a1 * b.y; acc[1][2] += a1 * b.z; acc[1][3] += a1 * b.w;
            acc[2][0] += a2 * b.x; acc[2][1] += a2 * b.y; acc[2][2] += a2 * b.z; acc[2][3] += a2 * b.w;
            acc[3][0] += a3 * b.x; acc[3][1] += a3 * b.y; acc[3][2] += a3 * b.z; acc[3][3] += a3 * b.w;
        }
        __syncthreads();
    }
#pragma unroll
    for (int i = 0; i < 4; i++) {
        float4 r = make_float4(acc[i][0], acc[i][1], acc[i][2], acc[i][3]);
        *(float4*)(Cp + (size_t)(bm + (ty << 2) + i) * N + bn + (tx << 2)) = r;
    }
}

__global__ void enc_reduce(const float* __restrict__ part, const float* __restrict__ bias,
                           float* __restrict__ out) {
    int i = blockIdx.x * 256 + threadIdx.x;
    float s = bias[i & 127];
#pragma unroll
    for (int c = 0; c < 32; c++) s += part[c * (Np * 128) + i];
    out[i] = fmaxf(s, 0.f);
}

// ---------------------------------------------------------------------------
// Residual + LayerNorm
// ---------------------------------------------------------------------------
__global__ void addln_kernel(float* __restrict__ z, const float* __restrict__ delta,
                             const float* __restrict__ gam, const float* __restrict__ bet) {
    int row = blockIdx.x, tid = threadIdx.x;
    size_t off = (size_t)row * Dm + tid;
    float vv = z[off] + delta[off];
    float mu = blockSum256(vv) * (1.f / 256.f);
    float dv = vv - mu;
    float var = blockSum256(dv * dv) * (1.f / 256.f);
    z[off] = dv * rsqrtf(var + 1e-5f) * gam[tid] + bet[tid];
}

// ---------------------------------------------------------------------------
// Encoder head + decoder hidden + assignment (exact fp32)
// ---------------------------------------------------------------------------
__global__ void low_kernel(const float* __restrict__ h1e, const float* __restrict__ eW2,
                           const float* __restrict__ eb2, const float* __restrict__ dW1,
                           const float* __restrict__ db1, const float* __restrict__ ctr,
                           float* __restrict__ low, float* __restrict__ hd,
                           int* __restrict__ idxp, float* __restrict__ dsq) {
    __shared__ float w2[256], dw[256], db[128], cc[10];
    int n = threadIdx.x;
    w2[n] = eW2[n];
    dw[n] = dW1[n];
    if (n < 128) db[n] = db1[n];
    if (n < 10)  cc[n] = ctr[n];
    __syncthreads();

    float a0 = eb2[0], a1 = eb2[1];
    for (int kk = 0; kk < 128; kk++) {
        float hv = h1e[n * 128 + kk];
        a0 += hv * w2[kk * 2 + 0];
        a1 += hv * w2[kk * 2 + 1];
    }
    float l0 = 1.f / (1.f + expf(-a0));
    float l1 = 1.f / (1.f + expf(-a1));
    low[n * 2 + 0] = l0;
    low[n * 2 + 1] = l1;
    for (int mm = 0; mm < 128; mm++) {
        float hv = l0 * dw[mm] + l1 * dw[128 + mm] + db[mm];
        hd[n * 128 + mm] = fmaxf(hv, 0.f);
    }
    int best = 0; float bd = 3.4e38f;
#pragma unroll
    for (int c = 0; c < Kc; c++) {
        float dx = l0 - cc[2 * c], dy = l1 - cc[2 * c + 1];
        float d2 = dx * dx + dy * dy;
        if (d2 < bd) { bd = d2; best = c; }
    }
    idxp[n] = best;
    dsq[n] = bd;
}

// ---------------------------------------------------------------------------
// Final losses + output
// ---------------------------------------------------------------------------
__global__ void final_kernel(const float* __restrict__ dsq, const int* __restrict__ idxp,
                             const float* __restrict__ low, const float* __restrict__ recpart,
                             float* __restrict__ out, int out_size) {
    __shared__ float sums[Kc], cnts[Kc];
    int tid = threadIdx.x;
    float d = dsq[tid];
    int my = idxp[tid];

    float inter = blockSum256(d) * (1.f / 256.f);

    if (tid < Kc) { sums[tid] = 0.f; cnts[tid] = 0.f; }
    __syncthreads();
    atomicAdd(&sums[my], d);
    atomicAdd(&cnts[my], 1.f);
    __syncthreads();

    bool mem = false;
    for (int j = 0; j < 256; j++) {
        if (idxp[j] == tid) { mem = true; break; }
    }
    float arr = mem ? 100.f : 0.f;

    float se = blockSum256(expf(arr - 100.f));
    float lse = logf(se) + 100.f;
    float logp = arr - lse;

    float klsum = blockSum256(-logf(256.f) - logp);
    float kl = klsum * (1.f / (256.f * 256.f));

    float rec = blockSum256(recpart[tid]) * (1.f / (256.f * 4096.f));

    if (tid == 0) {
        float intra = 0.f, ne = 0.f;
#pragma unroll
        for (int c = 0; c < Kc; c++) {
            if (cnts[c] > 0.f) { intra += sums[c] / fmaxf(cnts[c], 1.f); ne += 1.f; }
        }
        intra /= fmaxf(ne, 1.f);
        float loss = inter + intra + kl + rec;
        if (out_size > 0) out[0] = loss;
        if (out_size > 1) out[1] = kl;
    }
    if (2 + tid < out_size) out[2 + tid] = (float)my;
    int p0 = 258 + 2 * tid;
    if (p0 < out_size)     out[p0]     = low[2 * tid];
    if (p0 + 1 < out_size) out[p0 + 1] = low[2 * tid + 1];
}

// ---------------------------------------------------------------------------
// Host launcher
// ---------------------------------------------------------------------------
extern "C" void kernel_launch(void* const* d_in, const int* in_sizes, int n_in,
                              void* d_out, int out_size) {
    const float* x_seg  = (const float*)d_in[1];
    const float* emb_W  = (const float*)d_in[2];
    const float* emb_b  = (const float*)d_in[3];
    const float* Wq     = (const float*)d_in[4];
    const float* Wk     = (const float*)d_in[5];
    const float* Wv     = (const float*)d_in[6];
    const float* Wo     = (const float*)d_in[7];
    const float* W1     = (const float*)d_in[8];
    const float* b1     = (const float*)d_in[9];
    const float* W2     = (const float*)d_in[10];
    const float* b2     = (const float*)d_in[11];
    const float* ln1_g  = (const float*)d_in[12];
    const float* ln1_b  = (const float*)d_in[13];
    const float* ln2_g  = (const float*)d_in[14];
    const float* ln2_b  = (const float*)d_in[15];
    const float* enc_W1 = (const float*)d_in[16];
    const float* enc_b1 = (const float*)d_in[17];
    const float* enc_W2 = (const float*)d_in[18];
    const float* enc_b2 = (const float*)d_in[19];
    const float* dec_W1 = (const float*)d_in[20];
    const float* dec_b1 = (const float*)d_in[21];
    const float* dec_W2 = (const float*)d_in[22];
    const float* dec_b2 = (const float*)d_in[23];
    const float* centers = (const float*)d_in[24];

    float *z, *q, *k, *v, *o, *f, *h1, *encpart, *h1e, *low, *hd, *dsq, *recpart;
    int* idxp;
    cudaGetSymbolAddress((void**)&z,   g_z);
    cudaGetSymbolAddress((void**)&q,   g_q);
    cudaGetSymbolAddress((void**)&k,   g_k);
    cudaGetSymbolAddress((void**)&v,   g_v);
    cudaGetSymbolAddress((void**)&o,   g_o);
    cudaGetSymbolAddress((void**)&f,   g_f);
    cudaGetSymbolAddress((void**)&h1,  g_h1);
    cudaGetSymbolAddress((void**)&encpart, g_encpart);
    cudaGetSymbolAddress((void**)&h1e, g_h1e);
    cudaGetSymbolAddress((void**)&low, g_low);
    cudaGetSymbolAddress((void**)&hd,  g_hd);
    cudaGetSymbolAddress((void**)&dsq, g_dsq);
    cudaGetSymbolAddress((void**)&idxp, g_idx);
    cudaGetSymbolAddress((void**)&recpart, g_recpart);

    cudaFuncSetAttribute(gemm3,     cudaFuncAttributeMaxDynamicSharedMemorySize, GEMM3_SMEM);
    cudaFuncSetAttribute(gemm3_qkv, cudaFuncAttributeMaxDynamicSharedMemorySize, GEMM3_SMEM);
    cudaFuncSetAttribute(recgemm,   cudaFuncAttributeMaxDynamicSharedMemorySize, GEMM3_SMEM);
    cudaFuncSetAttribute(attn3,     cudaFuncAttributeMaxDynamicSharedMemorySize, AT3_SMEM_BYTES);

    embed_kernel<<<TOK, 256>>>(x_seg, emb_W, emb_b, z);

    for (int l = 0; l < 2; l++) {
        size_t wo = (size_t)l * Dm * Dm;
        gemm3_qkv<<<dim3(4, 64, 3), 128, GEMM3_SMEM>>>(z, Wq + wo, Wk + wo, Wv + wo, q, k, v);
        attn3<<<dim3(8, 64), 128, AT3_SMEM_BYTES>>>(q, k, v, o);
        gemm3<<<dim3(4, 64), 128, GEMM3_SMEM>>>(o, Wo + wo, nullptr, q, TOK, Dm, Dm, 0);
        addln_kernel<<<TOK, 256>>>(z, q, ln1_g + l * Dm, ln1_b + l * Dm);
        gemm3<<<dim3(16, 64), 128, GEMM3_SMEM>>>(z, W1 + (size_t)l * Dm * FFd, b1 + l * FFd,
                                                 h1, TOK, FFd, Dm, 2);
        gemm3<<<dim3(4, 64), 128, GEMM3_SMEM>>>(h1, W2 + (size_t)l * FFd * Dm, b2 + l * Dm,
                                                f, TOK, Dm, FFd, 1);
        addln_kernel<<<TOK, 256>>>(z, f, ln2_g + l * Dm, ln2_b + l * Dm);
    }

    gemm_splitk<<<dim3(2, 4, 32), 256>>>(z, ENCIN, enc_W1, 128, encpart, Np, 128, 128);
    enc_reduce<<<128, 256>>>(encpart, enc_b1, h1e);

    low_kernel<<<1, 256>>>(h1e, enc_W2, enc_b2, dec_W1, dec_b1, centers,
                           low, hd, idxp, dsq);
    recgemm<<<dim3(64, 4), 128, GEMM3_SMEM>>>(hd, dec_W2, dec_b2, z, recpart);
    final_kernel<<<1, 256>>>(dsq, idxp, low, recpart, (float*)d_out, out_size);
}

// round 6
// speedup vs baseline: 5.1153x; 1.0406x over previous
#include <cuda_runtime.h>
#include <math.h>

// ---------------------------------------------------------------------------
// Problem dims
// ---------------------------------------------------------------------------
#define TOK    4096
#define BATCH  8
#define SEQ    512
#define Dm     256
#define Hh     8
#define DHd    32
#define FFd    1024
#define Np     256
#define ENCIN  4096
#define Kc     5

// ---------------------------------------------------------------------------
// Scratch
// ---------------------------------------------------------------------------
__device__ float g_z [TOK * Dm];
__device__ float g_q [TOK * Dm];
__device__ float g_k [TOK * Dm];
__device__ float g_v [TOK * Dm];
__device__ float g_o [TOK * Dm];
__device__ float g_h1[TOK * FFd];
__device__ float g_encpart[32 * Np * 128];
__device__ float g_h1e[Np * 128];
__device__ float g_low[Np * 2];
__device__ float g_hd [Np * 128];
__device__ float g_dsq[Np];
__device__ int   g_idx[Np];
__device__ float g_recpart[Np];

// ---------------------------------------------------------------------------
__device__ __forceinline__ float blockSum256(float v) {
    __shared__ float red[8];
#pragma unroll
    for (int o = 16; o; o >>= 1) v += __shfl_xor_sync(0xffffffffu, v, o);
    if ((threadIdx.x & 31) == 0) red[threadIdx.x >> 5] = v;
    __syncthreads();
    float s = red[0] + red[1] + red[2] + red[3] + red[4] + red[5] + red[6] + red[7];
    __syncthreads();
    return s;
}

__device__ __forceinline__ float blockSum128(float v) {
    __shared__ float red[4];
#pragma unroll
    for (int o = 16; o; o >>= 1) v += __shfl_xor_sync(0xffffffffu, v, o);
    if ((threadIdx.x & 31) == 0) red[threadIdx.x >> 5] = v;
    __syncthreads();
    float s = red[0] + red[1] + red[2] + red[3];
    __syncthreads();
    return s;
}

__device__ __forceinline__ void cpasync16(void* smemp, const void* g) {
    unsigned s = (unsigned)__cvta_generic_to_shared(smemp);
    asm volatile("cp.async.cg.shared.global [%0], [%1], 16;" :: "r"(s), "l"(g));
}

#define MMA_TF32(acc, afr, b0, b1)                                            \
    asm volatile(                                                             \
        "mma.sync.aligned.m16n8k8.row.col.f32.tf32.tf32.f32 "                 \
        "{%0,%1,%2,%3},{%4,%5,%6,%7},{%8,%9},{%0,%1,%2,%3};"                  \
        : "+f"((acc)[0]), "+f"((acc)[1]), "+f"((acc)[2]), "+f"((acc)[3])      \
        : "r"((afr)[0]), "r"((afr)[1]), "r"((afr)[2]), "r"((afr)[3]),         \
          "r"(b0), "r"(b1))

// ---------------------------------------------------------------------------
// Embedding
// ---------------------------------------------------------------------------
__global__ void embed_kernel(const float* __restrict__ x, const float* __restrict__ W,
                             const float* __restrict__ b, float* __restrict__ z) {
    int n = blockIdx.x, d = threadIdx.x;
    float acc = b[d];
#pragma unroll
    for (int f = 0; f < 8; f++) acc += x[n * 8 + f] * W[f * Dm + d];
    z[(size_t)n * Dm + d] = acc;
}

// ---------------------------------------------------------------------------
// TF32 GEMM core: BM=BN=64, BK=32, 128 threads (4 warps, 2x2 of 32x32),
// 3-stage cp.async pipeline, raw fp32 bits into tf32 mma.
// ---------------------------------------------------------------------------
#define G3_A (64 * 36)
#define G3_B (32 * 72)
#define G3_STAGE (G3_A + G3_B)
#define GEMM3_SMEM (3 * G3_STAGE * 4)

__device__ __forceinline__ void gemm3_core(
        const float* __restrict__ A, const float* __restrict__ B,
        int N, int K, int bm, int bn, float acc[2][4][4]) {
    extern __shared__ float smem[];
    int tid = threadIdx.x, lane = tid & 31, w = tid >> 5;
    int wr = w >> 1, wc = w & 1;
    int r4 = lane >> 2, a4 = lane & 3;

#pragma unroll
    for (int mt = 0; mt < 2; mt++)
#pragma unroll
        for (int nt = 0; nt < 4; nt++)
#pragma unroll
            for (int c = 0; c < 4; c++) acc[mt][nt][c] = 0.f;

#define G3_LOAD(sidx, k0)                                                     \
    {                                                                         \
        float* Ad = smem + (sidx) * G3_STAGE;                                 \
        float* Bd = Ad + G3_A;                                                \
        _Pragma("unroll")                                                     \
        for (int j = 0; j < 4; j++) {                                         \
            int idx = tid + (j << 7);                                         \
            int row = idx >> 3, cc = (idx & 7) << 2;                          \
            cpasync16(&Ad[row * 36 + cc],                                     \
                      A + (size_t)(bm + row) * K + (k0) + cc);                \
        }                                                                     \
        _Pragma("unroll")                                                     \
        for (int j = 0; j < 4; j++) {                                         \
            int idx = tid + (j << 7);                                         \
            int row = idx >> 4, cc = (idx & 15) << 2;                         \
            cpasync16(&Bd[row * 72 + cc],                                     \
                      B + (size_t)((k0) + row) * N + bn + cc);                \
        }                                                                     \
        asm volatile("cp.async.commit_group;");                               \
    }

    int KT = K >> 5;
    G3_LOAD(0, 0);
    if (KT > 1) G3_LOAD(1, 32);

    int s = 0;
    for (int kt = 0; kt < KT; kt++) {
        if (kt + 1 < KT) asm volatile("cp.async.wait_group 1;");
        else             asm volatile("cp.async.wait_group 0;");
        __syncthreads();
        if (kt + 2 < KT) {
            int sn = s + 2; if (sn >= 3) sn -= 3;
            G3_LOAD(sn, (kt + 2) << 5);
        }
        const float* Am = smem + s * G3_STAGE;
        const float* Bm = Am + G3_A;
#pragma unroll
        for (int ks = 0; ks < 4; ks++) {
            int kd = (ks << 3) + a4;
            unsigned afr[2][4];
#pragma unroll
            for (int mt = 0; mt < 2; mt++) {
                int r = wr * 32 + mt * 16 + r4;
                afr[mt][0] = __float_as_uint(Am[r * 36 + kd]);
                afr[mt][1] = __float_as_uint(Am[(r + 8) * 36 + kd]);
                afr[mt][2] = __float_as_uint(Am[r * 36 + kd + 4]);
                afr[mt][3] = __float_as_uint(Am[(r + 8) * 36 + kd + 4]);
            }
#pragma unroll
            for (int nt = 0; nt < 4; nt++) {
                int n = wc * 32 + (nt << 3) + r4;
                unsigned b0 = __float_as_uint(Bm[kd * 72 + n]);
                unsigned b1 = __float_as_uint(Bm[(kd + 4) * 72 + n]);
#pragma unroll
                for (int mt = 0; mt < 2; mt++) MMA_TF32(acc[mt][nt], afr[mt], b0, b1);
            }
        }
        __syncthreads();
        s++; if (s >= 3) s -= 3;
    }
#undef G3_LOAD
}

__device__ __forceinline__ void gemm3_store(
        float acc[2][4][4], const float* __restrict__ bias, float* __restrict__ C,
        int N, int bm, int bn, int mode) {
    int tid = threadIdx.x, lane = tid & 31, w = tid >> 5;
    int wr = w >> 1, wc = w & 1;
    int r4 = lane >> 2, a4 = lane & 3;
#pragma unroll
    for (int mt = 0; mt < 2; mt++) {
        int row = bm + wr * 32 + mt * 16 + r4;
#pragma unroll
        for (int nt = 0; nt < 4; nt++) {
            int col = bn + wc * 32 + (nt << 3) + (a4 << 1);
            float bv0 = 0.f, bv1 = 0.f;
            if (mode >= 1) { bv0 = bias[col]; bv1 = bias[col + 1]; }
            float c0 = acc[mt][nt][0] + bv0, c1 = acc[mt][nt][1] + bv1;
            float c2 = acc[mt][nt][2] + bv0, c3 = acc[mt][nt][3] + bv1;
            if (mode == 2) {
                c0 = fmaxf(c0, 0.f); c1 = fmaxf(c1, 0.f);
                c2 = fmaxf(c2, 0.f); c3 = fmaxf(c3, 0.f);
            }
            *(float2*)(C + (size_t)row * N + col)       = make_float2(c0, c1);
            *(float2*)(C + (size_t)(row + 8) * N + col) = make_float2(c2, c3);
        }
    }
}

__global__ void __launch_bounds__(128) gemm3(
        const float* __restrict__ A, const float* __restrict__ B,
        const float* __restrict__ bias, float* __restrict__ C,
        int M, int N, int K, int mode) {
    float acc[2][4][4];
    int bm = blockIdx.y << 6, bn = blockIdx.x << 6;
    gemm3_core(A, B, N, K, bm, bn, acc);
    gemm3_store(acc, bias, C, N, bm, bn, mode);
}

__global__ void __launch_bounds__(128) gemm3_qkv(
        const float* __restrict__ A,
        const float* __restrict__ Wq, const float* __restrict__ Wk,
        const float* __restrict__ Wv,
        float* __restrict__ q, float* __restrict__ k, float* __restrict__ v) {
    const float* B; float* C;
    if (blockIdx.z == 0)      { B = Wq; C = q; }
    else if (blockIdx.z == 1) { B = Wk; C = k; }
    else                      { B = Wv; C = v; }
    float acc[2][4][4];
    int bm = blockIdx.y << 6, bn = blockIdx.x << 6;
    gemm3_core(A, B, Dm, Dm, bm, bn, acc);
    gemm3_store(acc, nullptr, C, Dm, bm, bn, 0);
}

// ---------------------------------------------------------------------------
// Fused GEMM + residual + LayerNorm.
// C = A[4096,K] @ W[K,256] (+bias); v = C + z; z = LN(v)*gamma+beta.
// BM=32, BN=256 (full rows per CTA), BK=32, 256 threads = 8 warps (2x4 of
// 16x64). 3-stage cp.async. Grid = 128 CTAs.
// ---------------------------------------------------------------------------
#define GLN_A (32 * 36)
#define GLN_B (32 * 264)
#define GLN_STAGE (GLN_A + GLN_B)
#define GLN_SMEM (3 * GLN_STAGE * 4)

__global__ void __launch_bounds__(256) gemmLN(
        const float* __restrict__ A, const float* __restrict__ W,
        const float* __restrict__ bias, float* __restrict__ z,
        const float* __restrict__ gam, const float* __restrict__ bet, int K) {
    extern __shared__ float smem[];
    int tid = threadIdx.x, lane = tid & 31, w = tid >> 5;
    int wr = w >> 2, wc = w & 3;
    int r4 = lane >> 2, a4 = lane & 3;
    int bm = blockIdx.x << 5;

    float acc[8][4];
#pragma unroll
    for (int nt = 0; nt < 8; nt++)
#pragma unroll
        for (int c = 0; c < 4; c++) acc[nt][c] = 0.f;

#define GLN_LOAD(sidx, k0)                                                    \
    {                                                                         \
        float* Ad = smem + (sidx) * GLN_STAGE;                                \
        float* Bd = Ad + GLN_A;                                               \
        {                                                                     \
            int row = tid >> 3, cc = (tid & 7) << 2;                          \
            cpasync16(&Ad[row * 36 + cc],                                     \
                      A + (size_t)(bm + row) * K + (k0) + cc);                \
        }                                                                     \
        _Pragma("unroll")                                                     \
        for (int j = 0; j < 8; j++) {                                         \
            int idx = tid + (j << 8);                                         \
            int row = idx >> 6, cc = (idx & 63) << 2;                         \
            cpasync16(&Bd[row * 264 + cc],                                    \
                      W + (size_t)((k0) + row) * Dm + cc);                    \
        }                                                                     \
        asm volatile("cp.async.commit_group;");                               \
    }

    int KT = K >> 5;
    GLN_LOAD(0, 0);
    if (KT > 1) GLN_LOAD(1, 32);

    int s = 0;
    for (int kt = 0; kt < KT; kt++) {
        if (kt + 1 < KT) asm volatile("cp.async.wait_group 1;");
        else             asm volatile("cp.async.wait_group 0;");
        __syncthreads();
        if (kt + 2 < KT) {
            int sn = s + 2; if (sn >= 3) sn -= 3;
            GLN_LOAD(sn, (kt + 2) << 5);
        }
        const float* Am = smem + s * GLN_STAGE;
        const float* Bm = Am + GLN_A;
#pragma unroll
        for (int ks = 0; ks < 4; ks++) {
            int kd = (ks << 3) + a4;
            unsigned afr[4];
            int r = wr * 16 + r4;
            afr[0] = __float_as_uint(Am[r * 36 + kd]);
            afr[1] = __float_as_uint(Am[(r + 8) * 36 + kd]);
            afr[2] = __float_as_uint(Am[r * 36 + kd + 4]);
            afr[3] = __float_as_uint(Am[(r + 8) * 36 + kd + 4]);
#pragma unroll
            for (int nt = 0; nt < 8; nt++) {
                int n = wc * 64 + (nt << 3) + r4;
                unsigned b0 = __float_as_uint(Bm[kd * 264 + n]);
                unsigned b1 = __float_as_uint(Bm[(kd + 4) * 264 + n]);
                MMA_TF32(acc[nt], afr, b0, b1);
            }
        }
        __syncthreads();
        s++; if (s >= 3) s -= 3;
    }
#undef GLN_LOAD

    // ---- epilogue: v = acc + bias + z; LN over each 256-wide row ----
    int row0 = bm + wr * 16 + r4;       // global rows
    int row1 = row0 + 8;
    int rl0 = wr * 16 + r4, rl1 = rl0 + 8;  // local rows 0..31
    float v0[16], v1[16];
    float s0 = 0.f, s1 = 0.f;
#pragma unroll
    for (int nt = 0; nt < 8; nt++) {
        int col = wc * 64 + (nt << 3) + (a4 << 1);
        float bb0 = 0.f, bb1 = 0.f;
        if (bias) { bb0 = bias[col]; bb1 = bias[col + 1]; }
        float2 z0 = *(const float2*)(z + (size_t)row0 * Dm + col);
        float2 z1 = *(const float2*)(z + (size_t)row1 * Dm + col);
        float a0 = acc[nt][0] + bb0 + z0.x;
        float a1 = acc[nt][1] + bb1 + z0.y;
        float a2 = acc[nt][2] + bb0 + z1.x;
        float a3 = acc[nt][3] + bb1 + z1.y;
        v0[nt * 2] = a0; v0[nt * 2 + 1] = a1;
        v1[nt * 2] = a2; v1[nt * 2 + 1] = a3;
        s0 += a0 + a1; s1 += a2 + a3;
    }
    // reduce over a4 (4 contiguous lanes share a row-segment group)
    s0 += __shfl_xor_sync(0xffffffffu, s0, 1);
    s0 += __shfl_xor_sync(0xffffffffu, s0, 2);
    s1 += __shfl_xor_sync(0xffffffffu, s1, 1);
    s1 += __shfl_xor_sync(0xffffffffu, s1, 2);
    float* red = smem;                  // reuse: [32][4]
    if (a4 == 0) { red[rl0 * 4 + wc] = s0; red[rl1 * 4 + wc] = s1; }
    __syncthreads();
    float mu0 = (red[rl0 * 4] + red[rl0 * 4 + 1] + red[rl0 * 4 + 2] + red[rl0 * 4 + 3]) * (1.f / 256.f);
    float mu1 = (red[rl1 * 4] + red[rl1 * 4 + 1] + red[rl1 * 4 + 2] + red[rl1 * 4 + 3]) * (1.f / 256.f);
    __syncthreads();
    float q0 = 0.f, q1 = 0.f;
#pragma unroll
    for (int i = 0; i < 16; i++) {
        float d0 = v0[i] - mu0, d1 = v1[i] - mu1;
        q0 += d0 * d0; q1 += d1 * d1;
    }
    q0 += __shfl_xor_sync(0xffffffffu, q0, 1);
    q0 += __shfl_xor_sync(0xffffffffu, q0, 2);
    q1 += __shfl_xor_sync(0xffffffffu, q1, 1);
    q1 += __shfl_xor_sync(0xffffffffu, q1, 2);
    if (a4 == 0) { red[rl0 * 4 + wc] = q0; red[rl1 * 4 + wc] = q1; }
    __syncthreads();
    float var0 = (red[rl0 * 4] + red[rl0 * 4 + 1] + red[rl0 * 4 + 2] + red[rl0 * 4 + 3]) * (1.f / 256.f);
    float var1 = (red[rl1 * 4] + red[rl1 * 4 + 1] + red[rl1 * 4 + 2] + red[rl1 * 4 + 3]) * (1.f / 256.f);
    float rs0 = rsqrtf(var0 + 1e-5f), rs1 = rsqrtf(var1 + 1e-5f);
#pragma unroll
    for (int nt = 0; nt < 8; nt++) {
        int col = wc * 64 + (nt << 3) + (a4 << 1);
        float g0 = gam[col], g1 = gam[col + 1];
        float be0 = bet[col], be1 = bet[col + 1];
        *(float2*)(z + (size_t)row0 * Dm + col) = make_float2(
            (v0[nt * 2] - mu0) * rs0 * g0 + be0,
            (v0[nt * 2 + 1] - mu0) * rs0 * g1 + be1);
        *(float2*)(z + (size_t)row1 * Dm + col) = make_float2(
            (v1[nt * 2] - mu1) * rs1 * g0 + be0,
            (v1[nt * 2 + 1] - mu1) * rs1 * g1 + be1);
    }
}

// ---------------------------------------------------------------------------
// Reconstruction loss GEMM (tf32) with L1 epilogue
// ---------------------------------------------------------------------------
__global__ void __launch_bounds__(128) recgemm(
        const float* __restrict__ hd, const float* __restrict__ W2,
        const float* __restrict__ b2, const float* __restrict__ pts,
        float* __restrict__ part) {
    float acc[2][4][4];
    int bm = blockIdx.y << 6, bn = blockIdx.x << 6;
    gemm3_core(hd, W2, ENCIN, 128, bm, bn, acc);

    int tid = threadIdx.x, lane = tid & 31, w = tid >> 5;
    int wr = w >> 1, wc = w & 1;
    int r4 = lane >> 2, a4 = lane & 3;
    float local = 0.f;
#pragma unroll
    for (int mt = 0; mt < 2; mt++) {
        int row = bm + wr * 32 + mt * 16 + r4;
#pragma unroll
        for (int nt = 0; nt < 4; nt++) {
            int col = bn + wc * 32 + (nt << 3) + (a4 << 1);
            float bv0 = b2[col], bv1 = b2[col + 1];
            float2 p0 = *(const float2*)(pts + (size_t)row * ENCIN + col);
            float2 p1 = *(const float2*)(pts + (size_t)(row + 8) * ENCIN + col);
            local += fabsf(p0.x - (acc[mt][nt][0] + bv0));
            local += fabsf(p0.y - (acc[mt][nt][1] + bv1));
            local += fabsf(p1.x - (acc[mt][nt][2] + bv0));
            local += fabsf(p1.y - (acc[mt][nt][3] + bv1));
        }
    }
    float s = blockSum128(local);
    if (tid == 0) part[blockIdx.y * gridDim.x + blockIdx.x] = s;
}

// ---------------------------------------------------------------------------
// TF32-MMA flash attention
// ---------------------------------------------------------------------------
#define AT3_SMEM_FLOATS (64 * 36 + 128 * 36 + 128 * 40 + 4 * 16 * 132)
#define AT3_SMEM_BYTES  (AT3_SMEM_FLOATS * 4)

__global__ void __launch_bounds__(128, 2) attn3(
        const float* __restrict__ qg, const float* __restrict__ kg,
        const float* __restrict__ vg, float* __restrict__ og) {
    extern __shared__ float sm[];
    float* Qs = sm;
    float* Ks = Qs + 64 * 36;
    float* Vs = Ks + 128 * 36;
    float* Ps = Vs + 128 * 40;

    int bh = blockIdx.y, b = bh >> 3, h = bh & 7;
    int qt = blockIdx.x;
    int tid = threadIdx.x, w = tid >> 5, lane = tid & 31;
    int r4 = lane >> 2, a4 = lane & 3;
    size_t base = (size_t)b * SEQ * Dm + h * DHd;
    const float scale = 0.17677669529663687f;

    for (int i = tid; i < 512; i += 128) {
        int row = i >> 3, c4 = (i & 7) << 2;
        float4 t = *(const float4*)(qg + base + (size_t)(qt * 64 + row) * Dm + c4);
        t.x *= scale; t.y *= scale; t.z *= scale; t.w *= scale;
        *(float4*)&Qs[row * 36 + c4] = t;
    }

    int q0 = w * 16;
    float* Pw = Ps + w * (16 * 132);
    float m0 = -1e30f, m1 = -1e30f, l0 = 0.f, l1 = 0.f;
    float oacc[4][4];
#pragma unroll
    for (int nt = 0; nt < 4; nt++)
#pragma unroll
        for (int c = 0; c < 4; c++) oacc[nt][c] = 0.f;

    for (int c = 0; c < 4; c++) {
        __syncthreads();
        for (int i = tid; i < 1024; i += 128) {
            int row = i >> 3, c4 = (i & 7) << 2;
            size_t goff = base + (size_t)(c * 128 + row) * Dm + c4;
            float4 tk = *(const float4*)(kg + goff);
            *(float4*)&Ks[row * 36 + c4] = tk;
            float4 tv = *(const float4*)(vg + goff);
            *(float4*)&Vs[row * 40 + c4] = tv;
        }
        __syncthreads();

        float S[16][4];
#pragma unroll
        for (int nt = 0; nt < 16; nt++)
#pragma unroll
            for (int j = 0; j < 4; j++) S[nt][j] = 0.f;

#pragma unroll
        for (int ks = 0; ks < 4; ks++) {
            int kd = (ks << 3) + a4;
            unsigned aq[4];
            int r = q0 + r4;
            aq[0] = __float_as_uint(Qs[r * 36 + kd]);
            aq[1] = __float_as_uint(Qs[(r + 8) * 36 + kd]);
            aq[2] = __float_as_uint(Qs[r * 36 + kd + 4]);
            aq[3] = __float_as_uint(Qs[(r + 8) * 36 + kd + 4]);
#pragma unroll
            for (int nt = 0; nt < 16; nt++) {
                int key = (nt << 3) + r4;
                unsigned b0 = __float_as_uint(Ks[key * 36 + kd]);
                unsigned b1 = __float_as_uint(Ks[key * 36 + kd + 4]);
                MMA_TF32(S[nt], aq, b0, b1);
            }
        }

        float mxa = -1e30f, mxb = -1e30f;
#pragma unroll
        for (int nt = 0; nt < 16; nt++) {
            mxa = fmaxf(mxa, fmaxf(S[nt][0], S[nt][1]));
            mxb = fmaxf(mxb, fmaxf(S[nt][2], S[nt][3]));
        }
#pragma unroll
        for (int off = 1; off < 4; off <<= 1) {
            mxa = fmaxf(mxa, __shfl_xor_sync(0xffffffffu, mxa, off));
            mxb = fmaxf(mxb, __shfl_xor_sync(0xffffffffu, mxb, off));
        }
        float mna = fmaxf(m0, mxa), mnb = fmaxf(m1, mxb);
        float corra = __expf(m0 - mna), corrb = __expf(m1 - mnb);
        float sa = 0.f, sb = 0.f;
#pragma unroll
        for (int nt = 0; nt < 16; nt++) {
            float p0 = __expf(S[nt][0] - mna);
            float p1 = __expf(S[nt][1] - mna);
            float p2 = __expf(S[nt][2] - mnb);
            float p3 = __expf(S[nt][3] - mnb);
            sa += p0 + p1; sb += p2 + p3;
            int col = (nt << 3) + (a4 << 1);
            *(float2*)&Pw[r4 * 132 + col]       = make_float2(p0, p1);
            *(float2*)&Pw[(r4 + 8) * 132 + col] = make_float2(p2, p3);
        }
#pragma unroll
        for (int off = 1; off < 4; off <<= 1) {
            sa += __shfl_xor_sync(0xffffffffu, sa, off);
            sb += __shfl_xor_sync(0xffffffffu, sb, off);
        }
        l0 = l0 * corra + sa; m0 = mna;
        l1 = l1 * corrb + sb; m1 = mnb;
#pragma unroll
        for (int nt = 0; nt < 4; nt++) {
            oacc[nt][0] *= corra; oacc[nt][1] *= corra;
            oacc[nt][2] *= corrb; oacc[nt][3] *= corrb;
        }
        __syncwarp();

#pragma unroll
        for (int ks = 0; ks < 16; ks++) {
            int key = (ks << 3) + a4;
            unsigned ap[4];
            ap[0] = __float_as_uint(Pw[r4 * 132 + key]);
            ap[1] = __float_as_uint(Pw[(r4 + 8) * 132 + key]);
            ap[2] = __float_as_uint(Pw[r4 * 132 + key + 4]);
            ap[3] = __float_as_uint(Pw[(r4 + 8) * 132 + key + 4]);
#pragma unroll
            for (int nt = 0; nt < 4; nt++) {
                int dim = (nt << 3) + r4;
                unsigned b0 = __float_as_uint(Vs[key * 40 + dim]);
                unsigned b1 = __float_as_uint(Vs[(key + 4) * 40 + dim]);
                MMA_TF32(oacc[nt], ap, b0, b1);
            }
        }
    }

    float inva = 1.f / l0, invb = 1.f / l1;
    int rowa = qt * 64 + q0 + r4;
#pragma unroll
    for (int nt = 0; nt < 4; nt++) {
        int col = (nt << 3) + (a4 << 1);
        *(float2*)(og + base + (size_t)rowa * Dm + col) =
            make_float2(oacc[nt][0] * inva, oacc[nt][1] * inva);
        *(float2*)(og + base + (size_t)(rowa + 8) * Dm + col) =
            make_float2(oacc[nt][2] * invb, oacc[nt][3] * invb);
    }
}

// ---------------------------------------------------------------------------
// fp32 split-K GEMM (encoder path — exact)
// ---------------------------------------------------------------------------
__global__ void __launch_bounds__(256) gemm_splitk(
        const float* __restrict__ A, int lda, const float* __restrict__ B, int ldb,
        float* __restrict__ Cp, int M, int N, int Kchunk) {
    __shared__ float As[16][65];
    __shared__ float Bs[16][64];
    int zc = blockIdx.z;
    A  += zc * Kchunk;
    B  += (size_t)zc * Kchunk * ldb;
    Cp += (size_t)zc * M * N;
    int tid = threadIdx.x;
    int bm = blockIdx.y << 6, bn = blockIdx.x << 6;
    int tx = tid & 15, ty = tid >> 4;
    int arow = tid >> 2, acol = (tid & 3) << 2;
    int brow = tid >> 4, bcol = (tid & 15) << 2;

    float acc[4][4] = {};
    for (int k0 = 0; k0 < Kchunk; k0 += 16) {
        float4 a4 = *(const float4*)(A + (size_t)(bm + arow) * lda + k0 + acol);
        As[acol + 0][arow] = a4.x; As[acol + 1][arow] = a4.y;
        As[acol + 2][arow] = a4.z; As[acol + 3][arow] = a4.w;
        float4 b4 = *(const float4*)(B + (size_t)(k0 + brow) * ldb + bn + bcol);
        *(float4*)&Bs[brow][bcol] = b4;
        __syncthreads();
#pragma unroll
        for (int kk = 0; kk < 16; kk++) {
            float a0 = As[kk][(ty << 2) + 0], a1 = As[kk][(ty << 2) + 1];
            float a2 = As[kk][(ty << 2) + 2], a3 = As[kk][(ty << 2) + 3];
            float4 b = *(const float4*)&Bs[kk][tx << 2];
            acc[0][0] += a0 * b.x; acc[0][1] += a0 * b.y; acc[0][2] += a0 * b.z; acc[0][3] += a0 * b.w;
            acc[1][0] += a1 * b.x; acc[1][1] += a1 * b.y; acc[1][2] += a1 * b.z; acc[1][3] += a1 * b.w;
            acc[2][0] += a2 * b.x; acc[2][1] += a2 * b.y; acc[2][2] += a2 * b.z; acc[2][3] += a2 * b.w;
            acc[3][0] += a3 * b.x; acc[3][1] += a3 * b.y; acc[3][2] += a3 * b.z; acc[3][3] += a3 * b.w;
        }
        __syncthreads();
    }
#pragma unroll
    for (int i = 0; i < 4; i++) {
        float4 r = make_float4(acc[i][0], acc[i][1], acc[i][2], acc[i][3]);
        *(float4*)(Cp + (size_t)(bm + (ty << 2) + i) * N + bn + (tx << 2)) = r;
    }
}

__global__ void enc_reduce(const float* __restrict__ part, const float* __restrict__ bias,
                           float* __restrict__ out) {
    int i = blockIdx.x * 256 + threadIdx.x;
    float s = bias[i & 127];
#pragma unroll
    for (int c = 0; c < 32; c++) s += part[c * (Np * 128) + i];
    out[i] = fmaxf(s, 0.f);
}

// ---------------------------------------------------------------------------
// Encoder head + decoder hidden + assignment (exact fp32)
// ---------------------------------------------------------------------------
__global__ void low_kernel(const float* __restrict__ h1e, const float* __restrict__ eW2,
                           const float* __restrict__ eb2, const float* __restrict__ dW1,
                           const float* __restrict__ db1, const float* __restrict__ ctr,
                           float* __restrict__ low, float* __restrict__ hd,
                           int* __restrict__ idxp, float* __restrict__ dsq) {
    __shared__ float w2[256], dw[256], db[128], cc[10];
    int n = threadIdx.x;
    w2[n] = eW2[n];
    dw[n] = dW1[n];
    if (n < 128) db[n] = db1[n];
    if (n < 10)  cc[n] = ctr[n];
    __syncthreads();

    float a0 = eb2[0], a1 = eb2[1];
    for (int kk = 0; kk < 128; kk++) {
        float hv = h1e[n * 128 + kk];
        a0 += hv * w2[kk * 2 + 0];
        a1 += hv * w2[kk * 2 + 1];
    }
    float l0 = 1.f / (1.f + expf(-a0));
    float l1 = 1.f / (1.f + expf(-a1));
    low[n * 2 + 0] = l0;
    low[n * 2 + 1] = l1;
    for (int mm = 0; mm < 128; mm++) {
        float hv = l0 * dw[mm] + l1 * dw[128 + mm] + db[mm];
        hd[n * 128 + mm] = fmaxf(hv, 0.f);
    }
    int best = 0; float bd = 3.4e38f;
#pragma unroll
    for (int c = 0; c < Kc; c++) {
        float dx = l0 - cc[2 * c], dy = l1 - cc[2 * c + 1];
        float d2 = dx * dx + dy * dy;
        if (d2 < bd) { bd = d2; best = c; }
    }
    idxp[n] = best;
    dsq[n] = bd;
}

// ---------------------------------------------------------------------------
// Final losses + output
// ---------------------------------------------------------------------------
__global__ void final_kernel(const float* __restrict__ dsq, const int* __restrict__ idxp,
                             const float* __restrict__ low, const float* __restrict__ recpart,
                             float* __restrict__ out, int out_size) {
    __shared__ float sums[Kc], cnts[Kc];
    int tid = threadIdx.x;
    float d = dsq[tid];
    int my = idxp[tid];

    float inter = blockSum256(d) * (1.f / 256.f);

    if (tid < Kc) { sums[tid] = 0.f; cnts[tid] = 0.f; }
    __syncthreads();
    atomicAdd(&sums[my], d);
    atomicAdd(&cnts[my], 1.f);
    __syncthreads();

    bool mem = false;
    for (int j = 0; j < 256; j++) {
        if (idxp[j] == tid) { mem = true; break; }
    }
    float arr = mem ? 100.f : 0.f;

    float se = blockSum256(expf(arr - 100.f));
    float lse = logf(se) + 100.f;
    float logp = arr - lse;

    float klsum = blockSum256(-logf(256.f) - logp);
    float kl = klsum * (1.f / (256.f * 256.f));

    float rec = blockSum256(recpart[tid]) * (1.f / (256.f * 4096.f));

    if (tid == 0) {
        float intra = 0.f, ne = 0.f;
#pragma unroll
        for (int c = 0; c < Kc; c++) {
            if (cnts[c] > 0.f) { intra += sums[c] / fmaxf(cnts[c], 1.f); ne += 1.f; }
        }
        intra /= fmaxf(ne, 1.f);
        float loss = inter + intra + kl + rec;
        if (out_size > 0) out[0] = loss;
        if (out_size > 1) out[1] = kl;
    }
    if (2 + tid < out_size) out[2 + tid] = (float)my;
    int p0 = 258 + 2 * tid;
    if (p0 < out_size)     out[p0]     = low[2 * tid];
    if (p0 + 1 < out_size) out[p0 + 1] = low[2 * tid + 1];
}

// ---------------------------------------------------------------------------
// Host launcher
// ---------------------------------------------------------------------------
extern "C" void kernel_launch(void* const* d_in, const int* in_sizes, int n_in,
                              void* d_out, int out_size) {
    const float* x_seg  = (const float*)d_in[1];
    const float* emb_W  = (const float*)d_in[2];
    const float* emb_b  = (const float*)d_in[3];
    const float* Wq     = (const float*)d_in[4];
    const float* Wk     = (const float*)d_in[5];
    const float* Wv     = (const float*)d_in[6];
    const float* Wo     = (const float*)d_in[7];
    const float* W1     = (const float*)d_in[8];
    const float* b1     = (const float*)d_in[9];
    const float* W2     = (const float*)d_in[10];
    const float* b2     = (const float*)d_in[11];
    const float* ln1_g  = (const float*)d_in[12];
    const float* ln1_b  = (const float*)d_in[13];
    const float* ln2_g  = (const float*)d_in[14];
    const float* ln2_b  = (const float*)d_in[15];
    const float* enc_W1 = (const float*)d_in[16];
    const float* enc_b1 = (const float*)d_in[17];
    const float* enc_W2 = (const float*)d_in[18];
    const float* enc_b2 = (const float*)d_in[19];
    const float* dec_W1 = (const float*)d_in[20];
    const float* dec_b1 = (const float*)d_in[21];
    const float* dec_W2 = (const float*)d_in[22];
    const float* dec_b2 = (const float*)d_in[23];
    const float* centers = (const float*)d_in[24];

    float *z, *q, *k, *v, *o, *h1, *encpart, *h1e, *low, *hd, *dsq, *recpart;
    int* idxp;
    cudaGetSymbolAddress((void**)&z,   g_z);
    cudaGetSymbolAddress((void**)&q,   g_q);
    cudaGetSymbolAddress((void**)&k,   g_k);
    cudaGetSymbolAddress((void**)&v,   g_v);
    cudaGetSymbolAddress((void**)&o,   g_o);
    cudaGetSymbolAddress((void**)&h1,  g_h1);
    cudaGetSymbolAddress((void**)&encpart, g_encpart);
    cudaGetSymbolAddress((void**)&h1e, g_h1e);
    cudaGetSymbolAddress((void**)&low, g_low);
    cudaGetSymbolAddress((void**)&hd,  g_hd);
    cudaGetSymbolAddress((void**)&dsq, g_dsq);
    cudaGetSymbolAddress((void**)&idxp, g_idx);
    cudaGetSymbolAddress((void**)&recpart, g_recpart);

    cudaFuncSetAttribute(gemm3,     cudaFuncAttributeMaxDynamicSharedMemorySize, GEMM3_SMEM);
    cudaFuncSetAttribute(gemm3_qkv, cudaFuncAttributeMaxDynamicSharedMemorySize, GEMM3_SMEM);
    cudaFuncSetAttribute(recgemm,   cudaFuncAttributeMaxDynamicSharedMemorySize, GEMM3_SMEM);
    cudaFuncSetAttribute(gemmLN,    cudaFuncAttributeMaxDynamicSharedMemorySize, GLN_SMEM);
    cudaFuncSetAttribute(attn3,     cudaFuncAttributeMaxDynamicSharedMemorySize, AT3_SMEM_BYTES);

    embed_kernel<<<TOK, 256>>>(x_seg, emb_W, emb_b, z);

    for (int l = 0; l < 2; l++) {
        size_t wo = (size_t)l * Dm * Dm;
        gemm3_qkv<<<dim3(4, 64, 3), 128, GEMM3_SMEM>>>(z, Wq + wo, Wk + wo, Wv + wo, q, k, v);
        attn3<<<dim3(8, 64), 128, AT3_SMEM_BYTES>>>(q, k, v, o);
        // Wo projection + residual + ln1, fused
        gemmLN<<<128, 256, GLN_SMEM>>>(o, Wo + wo, nullptr, z,
                                       ln1_g + l * Dm, ln1_b + l * Dm, Dm);
        gemm3<<<dim3(16, 64), 128, GEMM3_SMEM>>>(z, W1 + (size_t)l * Dm * FFd, b1 + l * FFd,
                                                 h1, TOK, FFd, Dm, 2);
        // FF2 + residual + ln2, fused
        gemmLN<<<128, 256, GLN_SMEM>>>(h1, W2 + (size_t)l * FFd * Dm, b2 + l * Dm, z,
                                       ln2_g + l * Dm, ln2_b + l * Dm, FFd);
    }

    gemm_splitk<<<dim3(2, 4, 32), 256>>>(z, ENCIN, enc_W1, 128, encpart, Np, 128, 128);
    enc_reduce<<<128, 256>>>(encpart, enc_b1, h1e);

    low_kernel<<<1, 256>>>(h1e, enc_W2, enc_b2, dec_W1, dec_b1, centers,
                           low, hd, idxp, dsq);
    recgemm<<<dim3(64, 4), 128, GEMM3_SMEM>>>(hd, dec_W2, dec_b2, z, recpart);
    final_kernel<<<1, 256>>>(dsq, idxp, low, recpart, (float*)d_out, out_size);
}